// round 4
// baseline (speedup 1.0000x reference)
#include <cuda_runtime.h>
#include <math.h>

#define BB 8
#define CC 384
#define NN 1024
#define NH 8
#define HD 48
#define HID 192
#define NBIAS 3969            // 63*63 distinct (dh,dw) pairs
#define QK_SCALE 0.14433756729740643f  // 48^-0.5

// Scratch (static device globals; runtime allocation is forbidden)
__device__ float g_bias[NH * NBIAS];          // [head][dh+31][dw+31]
__device__ float g_Q[BB*NH*NN*HD];            // [b][h][n][d], pre-scaled
__device__ float g_K[BB*NH*NN*HD];
__device__ float g_V[BB*NH*NN*HD];
__device__ float g_att[BB*NN*CC];             // attention output, [b][n][c]

// ---------------------------------------------------------------------------
// 1) Relative-bias MLP over the 63x63 unique relative offsets
// ---------------------------------------------------------------------------
__global__ void bias_kernel(const float* __restrict__ w1, const float* __restrict__ b1,
                            const float* __restrict__ w2, const float* __restrict__ b2) {
    int p = blockIdx.x * blockDim.x + threadIdx.x;
    if (p >= NBIAS) return;
    int dh = p / 63, dw = p % 63;
    float rh = (float)(dh - 31) * (1.0f / 31.0f);
    float rw = (float)(dw - 31) * (1.0f / 31.0f);
    float out[NH];
#pragma unroll
    for (int h = 0; h < NH; h++) out[h] = b2[h];
    for (int k = 0; k < HID; k++) {
        float pre = rh * w1[k] + rw * w1[HID + k] + b1[k];
        float g = 0.5f * pre * (1.0f + erff(pre * 0.70710678118654752f)); // exact GELU
#pragma unroll
        for (int h = 0; h < NH; h++) out[h] += g * w2[k * NH + h];
    }
#pragma unroll
    for (int h = 0; h < NH; h++) g_bias[h * NBIAS + p] = out[h];
}

// ---------------------------------------------------------------------------
// 2) QKV GEMM: tokens[8192,384] @ qkv_w[384,1152] + b  -> scatter to Q/K/V
//    tokens[row=b*1024+n][c] = x[b][c][n]  (x is [B,C,H,W])
// ---------------------------------------------------------------------------
#define BM 64
#define BN 64
#define BK 16

__global__ __launch_bounds__(256) void qkv_kernel(const float* __restrict__ x,
                                                  const float* __restrict__ w,
                                                  const float* __restrict__ bias) {
    __shared__ float As[BK][BM];   // As[k][m]; x access is already k-major -> coalesced
    __shared__ float Bs[BK][BN];
    const int rowBase = blockIdx.y * BM;
    const int colBase = blockIdx.x * BN;
    const int b  = rowBase >> 10;       // 1024 % 64 == 0 -> whole tile in one batch
    const int n0 = rowBase & 1023;
    const int tid = threadIdx.x;
    const int ty = tid >> 4, tx = tid & 15;
    float acc[4][4] = {};

    for (int k0 = 0; k0 < CC; k0 += BK) {
#pragma unroll
        for (int i = tid; i < BK * BM; i += 256) {     // m fastest -> coalesced in n
            int kk = i >> 6, m = i & 63;
            As[kk][m] = x[(b * CC + k0 + kk) * NN + n0 + m];
        }
#pragma unroll
        for (int i = tid; i < BK * BN; i += 256) {
            int kk = i >> 6, nn = i & 63;
            Bs[kk][nn] = w[(k0 + kk) * (3 * CC) + colBase + nn];
        }
        __syncthreads();
#pragma unroll
        for (int kk = 0; kk < BK; kk++) {
            float a[4], bb[4];
#pragma unroll
            for (int i = 0; i < 4; i++) a[i] = As[kk][ty * 4 + i];
#pragma unroll
            for (int j = 0; j < 4; j++) bb[j] = Bs[kk][tx * 4 + j];
#pragma unroll
            for (int i = 0; i < 4; i++)
#pragma unroll
                for (int j = 0; j < 4; j++) acc[i][j] += a[i] * bb[j];
        }
        __syncthreads();
    }

#pragma unroll
    for (int i = 0; i < 4; i++) {
        int n = n0 + ty * 4 + i;
#pragma unroll
        for (int j = 0; j < 4; j++) {
            int col = colBase + tx * 4 + j;
            float v = acc[i][j] + bias[col];
            int which = col / CC;            // block never straddles which (384 % 64 == 0)
            int c = col - which * CC;
            int head = c / HD;
            int d = c - head * HD;
            float* dst = (which == 0) ? g_Q : (which == 1 ? g_K : g_V);
            if (which == 0) v *= QK_SCALE;
            dst[(((b * NH) + head) * NN + n) * HD + d] = v;
        }
    }
}

// ---------------------------------------------------------------------------
// 3) Attention: one thread owns one query (q[48], o[48] in regs, per-thread
//    online softmax). K/V streamed via smem in 32-key tiles; bias table in smem.
// ---------------------------------------------------------------------------
#define TK 32

__global__ __launch_bounds__(128, 3) void attn_kernel() {
    __shared__ float Ks[TK * HD];        // 6 KB
    __shared__ float Vs[TK * HD];        // 6 KB
    __shared__ float sS[TK * 128];       // 16 KB  (per-thread score column)
    __shared__ float sBias[NBIAS];       // 15.5 KB

    const int b = blockIdx.z, h = blockIdx.y, qb = blockIdx.x;
    const int tid = threadIdx.x;

    for (int i = tid; i < NBIAS; i += 128) sBias[i] = g_bias[h * NBIAS + i];

    const int n = qb * 128 + tid;
    const int ih = n >> 5, iw = n & 31;

    const float* Qp = g_Q + (((b * NH + h) * NN) + n) * HD;
    float q[HD];
#pragma unroll
    for (int t = 0; t < HD / 4; t++) {
        float4 v = ((const float4*)Qp)[t];
        q[t*4] = v.x; q[t*4+1] = v.y; q[t*4+2] = v.z; q[t*4+3] = v.w;
    }

    const float4* Kg = (const float4*)(g_K + ((b * NH + h) * NN) * HD);
    const float4* Vg = (const float4*)(g_V + ((b * NH + h) * NN) * HD);

    float o[HD] = {};
    float m = -1e30f, l = 0.0f;

    for (int kt = 0; kt < NN; kt += TK) {
        __syncthreads();                       // previous tile fully consumed
        const int base4 = kt * (HD / 4);
#pragma unroll
        for (int i = tid; i < TK * HD / 4; i += 128) {
            ((float4*)Ks)[i] = Kg[base4 + i];
            ((float4*)Vs)[i] = Vg[base4 + i];
        }
        __syncthreads();

        float mt = m;
#pragma unroll 4
        for (int j = 0; j < TK; j++) {
            const float4* kr = (const float4*)(Ks + j * HD);
            float s = 0.0f;
#pragma unroll
            for (int t = 0; t < HD / 4; t++) {
                float4 kv = kr[t];
                s += q[t*4] * kv.x + q[t*4+1] * kv.y + q[t*4+2] * kv.z + q[t*4+3] * kv.w;
            }
            int key = kt + j;
            int dhi = ih - (key >> 5) + 31;
            int dwi = iw - (key & 31) + 31;
            s += sBias[dhi * 63 + dwi];
            sS[j * 128 + tid] = s;             // own column, conflict-free, no sync needed
            mt = fmaxf(mt, s);
        }

        float alpha = __expf(m - mt);          // tile-amortized rescale
        m = mt;
        l *= alpha;
#pragma unroll
        for (int d = 0; d < HD; d++) o[d] *= alpha;

#pragma unroll 2
        for (int j = 0; j < TK; j++) {
            float p = __expf(sS[j * 128 + tid] - m);
            l += p;
            const float4* vr = (const float4*)(Vs + j * HD);
#pragma unroll
            for (int t = 0; t < HD / 4; t++) {
                float4 vv = vr[t];
                o[t*4]   += p * vv.x;
                o[t*4+1] += p * vv.y;
                o[t*4+2] += p * vv.z;
                o[t*4+3] += p * vv.w;
            }
        }
    }

    const float inv = 1.0f / l;
    float* op = g_att + (b * NN + n) * CC + h * HD;   // [b][n][c=h*48+d]
#pragma unroll
    for (int t = 0; t < HD / 4; t++) {
        ((float4*)op)[t] = make_float4(o[t*4] * inv, o[t*4+1] * inv,
                                       o[t*4+2] * inv, o[t*4+3] * inv);
    }
}

// ---------------------------------------------------------------------------
// 4) Proj GEMM: g_att[8192,384] @ proj_w[384,384] + b -> out [B,C,H,W]
// ---------------------------------------------------------------------------
__global__ __launch_bounds__(256) void proj_kernel(const float* __restrict__ w,
                                                   const float* __restrict__ pb,
                                                   float* __restrict__ out) {
    __shared__ float As[BK][BM + 1];   // +1 pad: kk-fast store would otherwise 16-way conflict
    __shared__ float Bs[BK][BN];
    const int rowBase = blockIdx.y * BM;
    const int colBase = blockIdx.x * BN;
    const int b  = rowBase >> 10;
    const int n0 = rowBase & 1023;
    const int tid = threadIdx.x;
    const int ty = tid >> 4, tx = tid & 15;
    float acc[4][4] = {};

    for (int k0 = 0; k0 < CC; k0 += BK) {
#pragma unroll
        for (int i = tid; i < BM * BK; i += 256) {    // kk fastest -> coalesced (A row-major)
            int m = i >> 4, kk = i & 15;
            As[kk][m] = g_att[(rowBase + m) * CC + k0 + kk];
        }
#pragma unroll
        for (int i = tid; i < BK * BN; i += 256) {
            int kk = i >> 6, nn = i & 63;
            Bs[kk][nn] = w[(k0 + kk) * CC + colBase + nn];
        }
        __syncthreads();
#pragma unroll
        for (int kk = 0; kk < BK; kk++) {
            float a[4], bb[4];
#pragma unroll
            for (int i = 0; i < 4; i++) a[i] = As[kk][ty * 4 + i];
#pragma unroll
            for (int j = 0; j < 4; j++) bb[j] = Bs[kk][tx * 4 + j];
#pragma unroll
            for (int i = 0; i < 4; i++)
#pragma unroll
                for (int j = 0; j < 4; j++) acc[i][j] += a[i] * bb[j];
        }
        __syncthreads();
    }

#pragma unroll
    for (int i = 0; i < 4; i++) {
        int n = n0 + ty * 4 + i;
#pragma unroll
        for (int j = 0; j < 4; j++) {
            int c = colBase + tx * 4 + j;
            out[(b * CC + c) * NN + n] = acc[i][j] + pb[c];  // [B,C,H,W] transpose write
        }
    }
}

// ---------------------------------------------------------------------------
extern "C" void kernel_launch(void* const* d_in, const int* in_sizes, int n_in,
                              void* d_out, int out_size) {
    const float* x      = (const float*)d_in[0];
    const float* qkv_w  = (const float*)d_in[1];
    const float* qkv_b  = (const float*)d_in[2];
    const float* proj_w = (const float*)d_in[3];
    const float* proj_b = (const float*)d_in[4];
    const float* mlp_w1 = (const float*)d_in[5];
    const float* mlp_b1 = (const float*)d_in[6];
    const float* mlp_w2 = (const float*)d_in[7];
    const float* mlp_b2 = (const float*)d_in[8];
    float* out = (float*)d_out;

    bias_kernel<<<(NBIAS + 255) / 256, 256>>>(mlp_w1, mlp_b1, mlp_w2, mlp_b2);
    qkv_kernel<<<dim3(3 * CC / BN, BB * NN / BM), 256>>>(x, qkv_w, qkv_b);
    attn_kernel<<<dim3(NN / 128, NH, BB), 128>>>();
    proj_kernel<<<dim3(CC / BN, BB * NN / BM), 256>>>(proj_w, proj_b, out);
}

// round 6
// speedup vs baseline: 1.1417x; 1.1417x over previous
#include <cuda_runtime.h>
#include <math.h>

#define BB 8
#define CC 384
#define NN 1024
#define NH 8
#define HD 48
#define HID 192
#define NBIAS 3969            // 63*63 distinct (dh,dw) pairs
#define QK_SCALE 0.14433756729740643f  // 48^-0.5

typedef unsigned long long u64;

// ---- packed f32x2 helpers (Blackwell: 2x fp32 throughput, PTX-only path) ----
__device__ __forceinline__ void fma2(u64 &d, u64 a, u64 b) {
    asm("fma.rn.f32x2 %0, %1, %2, %0;" : "+l"(d) : "l"(a), "l"(b));
}
__device__ __forceinline__ void mul2(u64 &d, u64 a, u64 b) {
    asm("mul.rn.f32x2 %0, %1, %2;" : "=l"(d) : "l"(a), "l"(b));
}
__device__ __forceinline__ void add2(u64 &d, u64 a, u64 b) {
    asm("add.rn.f32x2 %0, %1, %2;" : "=l"(d) : "l"(a), "l"(b));
}
__device__ __forceinline__ u64 pack2(float x, float y) {
    u64 r; asm("mov.b64 %0, {%1, %2};" : "=l"(r) : "f"(x), "f"(y)); return r;
}
__device__ __forceinline__ float2 unpack2(u64 v) {
    float2 r; asm("mov.b64 {%0, %1}, %2;" : "=f"(r.x), "=f"(r.y) : "l"(v)); return r;
}

// Scratch (static device globals; runtime allocation is forbidden)
__device__ float g_bias[NH * NBIAS];          // [head][dh+31][dw+31]
__device__ float g_Q[BB*NH*NN*HD];            // [b][h][n][d], pre-scaled
__device__ float g_K[BB*NH*NN*HD];
__device__ float g_V[BB*NH*NN*HD];
__device__ float g_att[BB*CC*NN];             // attention output, [b][c][n] (c = h*48+d)

// ---------------------------------------------------------------------------
// 1) Relative-bias MLP over the 63x63 unique relative offsets
// ---------------------------------------------------------------------------
__global__ void bias_kernel(const float* __restrict__ w1, const float* __restrict__ b1,
                            const float* __restrict__ w2, const float* __restrict__ b2) {
    int p = blockIdx.x * blockDim.x + threadIdx.x;
    if (p >= NBIAS) return;
    int dh = p / 63, dw = p % 63;
    float rh = (float)(dh - 31) * (1.0f / 31.0f);
    float rw = (float)(dw - 31) * (1.0f / 31.0f);
    float out[NH];
#pragma unroll
    for (int h = 0; h < NH; h++) out[h] = b2[h];
    for (int k = 0; k < HID; k++) {
        float pre = rh * w1[k] + rw * w1[HID + k] + b1[k];
        float g = 0.5f * pre * (1.0f + erff(pre * 0.70710678118654752f)); // exact GELU
#pragma unroll
        for (int h = 0; h < NH; h++) out[h] += g * w2[k * NH + h];
    }
#pragma unroll
    for (int h = 0; h < NH; h++) g_bias[h * NBIAS + p] = out[h];
}

// ---------------------------------------------------------------------------
// GEMM tiling: 128x128 block, 256 threads, 8x8 micro-tile, f32x2 inner product
// ---------------------------------------------------------------------------
#define GBM 128
#define GBN 128
#define GBK 16

// 2) QKV GEMM: tokens[8192,384] @ qkv_w[384,1152] + b -> scatter Q/K/V [b,h,n,d]
//    M = token rows (n), N = output cols. tokens[row][c] = x[b][c][n] (k-major).
__global__ __launch_bounds__(256) void qkv_kernel(const float* __restrict__ x,
                                                  const float* __restrict__ w,
                                                  const float* __restrict__ bias) {
    __shared__ __align__(16) float As[GBK][GBM];
    __shared__ __align__(16) float Bs[GBK][GBN];
    const int mBase = blockIdx.y * GBM;
    const int colBase = blockIdx.x * GBN;
    const int b  = mBase >> 10;          // 1024 % 128 == 0
    const int n0 = mBase & 1023;
    const int tid = threadIdx.x;
    const int ty = tid >> 4, tx = tid & 15;
    u64 acc[8][4] = {};

    for (int k0 = 0; k0 < CC; k0 += GBK) {
#pragma unroll
        for (int i = tid; i < GBK * GBM; i += 256) {   // m fastest -> coalesced in n
            int kk = i >> 7, m = i & 127;
            As[kk][m] = x[(b * CC + k0 + kk) * NN + n0 + m];
        }
#pragma unroll
        for (int i = tid; i < GBK * GBN; i += 256) {
            int kk = i >> 7, nn = i & 127;
            Bs[kk][nn] = w[(k0 + kk) * (3 * CC) + colBase + nn];
        }
        __syncthreads();
#pragma unroll
        for (int kk = 0; kk < GBK; kk++) {
            float4 a0 = *(const float4*)&As[kk][ty * 8];
            float4 a1 = *(const float4*)&As[kk][ty * 8 + 4];
            ulonglong2 bq0 = *(const ulonglong2*)&Bs[kk][tx * 8];
            ulonglong2 bq1 = *(const ulonglong2*)&Bs[kk][tx * 8 + 4];
            u64 bp[4] = { bq0.x, bq0.y, bq1.x, bq1.y };
            u64 ad[8] = { pack2(a0.x,a0.x), pack2(a0.y,a0.y), pack2(a0.z,a0.z), pack2(a0.w,a0.w),
                          pack2(a1.x,a1.x), pack2(a1.y,a1.y), pack2(a1.z,a1.z), pack2(a1.w,a1.w) };
#pragma unroll
            for (int i = 0; i < 8; i++)
#pragma unroll
                for (int jp = 0; jp < 4; jp++) fma2(acc[i][jp], ad[i], bp[jp]);
        }
        __syncthreads();
    }

    // Epilogue: each thread owns 8 consecutive cols (8 | 48, so never crosses a
    // head or Q/K/V boundary) x 8 consecutive rows (n).
    const int col0 = colBase + tx * 8;
    const int which = col0 / CC;
    const int cc0 = col0 - which * CC;
    const int head = cc0 / HD;
    const int d0 = cc0 - head * HD;
    float* dst = (which == 0) ? g_Q : (which == 1 ? g_K : g_V);
    const float scale = (which == 0) ? QK_SCALE : 1.0f;
    float bsv[8];
#pragma unroll
    for (int j = 0; j < 8; j++) bsv[j] = bias[col0 + j];

#pragma unroll
    for (int i = 0; i < 8; i++) {
        int n = n0 + ty * 8 + i;
        float vv[8];
#pragma unroll
        for (int jp = 0; jp < 4; jp++) {
            float2 u = unpack2(acc[i][jp]);
            vv[2*jp]   = (u.x + bsv[2*jp])   * scale;
            vv[2*jp+1] = (u.y + bsv[2*jp+1]) * scale;
        }
        float* p = dst + ((size_t)((b * NH + head) * NN + n)) * HD + d0;
        ((float4*)p)[0] = make_float4(vv[0], vv[1], vv[2], vv[3]);
        ((float4*)p)[1] = make_float4(vv[4], vv[5], vv[6], vv[7]);
    }
}

// ---------------------------------------------------------------------------
// 3) Attention: one thread per query, f32x2 packed dot/accumulate.
// ---------------------------------------------------------------------------
#define TK 32

__global__ __launch_bounds__(128, 3) void attn_kernel() {
    __shared__ __align__(16) float Ks[TK * HD];   // 6 KB
    __shared__ __align__(16) float Vs[TK * HD];   // 6 KB
    __shared__ float sS[TK * 128];                // 16 KB (per-thread score column)
    __shared__ float sBias[NBIAS];                // 15.5 KB

    const int b = blockIdx.z, h = blockIdx.y, qb = blockIdx.x;
    const int tid = threadIdx.x;

    for (int i = tid; i < NBIAS; i += 128) sBias[i] = g_bias[h * NBIAS + i];

    const int n = qb * 128 + tid;
    const int ih = n >> 5, iw = n & 31;

    const float4* Qp = (const float4*)(g_Q + (((b * NH + h) * NN) + n) * HD);
    u64 q2[24];
#pragma unroll
    for (int t = 0; t < 12; t++) {
        float4 v = Qp[t];
        q2[2*t]   = pack2(v.x, v.y);
        q2[2*t+1] = pack2(v.z, v.w);
    }

    const float4* Kg = (const float4*)(g_K + ((b * NH + h) * NN) * HD);
    const float4* Vg = (const float4*)(g_V + ((b * NH + h) * NN) * HD);

    u64 o2[24] = {};
    float m = -1e30f, l = 0.0f;

    for (int kt = 0; kt < NN; kt += TK) {
        __syncthreads();                       // previous tile fully consumed
        const int base4 = kt * (HD / 4);
#pragma unroll
        for (int i = tid; i < TK * HD / 4; i += 128) {
            ((float4*)Ks)[i] = Kg[base4 + i];
            ((float4*)Vs)[i] = Vg[base4 + i];
        }
        __syncthreads();

        float mt = m;
#pragma unroll 4
        for (int j = 0; j < TK; j++) {
            const ulonglong2* kr = (const ulonglong2*)(Ks + j * HD);
            u64 sa = 0, sb = 0;                // packed zeros
#pragma unroll
            for (int t = 0; t < 12; t++) {
                ulonglong2 kp = kr[t];
                fma2(sa, q2[2*t],   kp.x);
                fma2(sb, q2[2*t+1], kp.y);
            }
            add2(sa, sa, sb);
            float2 su = unpack2(sa);
            float s = su.x + su.y;
            int key = kt + j;
            int dhi = ih - (key >> 5) + 31;
            int dwi = iw - (key & 31) + 31;
            s += sBias[dhi * 63 + dwi];
            sS[j * 128 + tid] = s;             // own column, conflict-free
            mt = fmaxf(mt, s);
        }

        float alpha = __expf(m - mt);          // tile-amortized rescale
        m = mt;
        l *= alpha;
        u64 a2 = pack2(alpha, alpha);
#pragma unroll
        for (int t = 0; t < 24; t++) mul2(o2[t], o2[t], a2);

#pragma unroll 2
        for (int j = 0; j < TK; j++) {
            float p = __expf(sS[j * 128 + tid] - m);
            l += p;
            u64 p2 = pack2(p, p);
            const ulonglong2* vr = (const ulonglong2*)(Vs + j * HD);
#pragma unroll
            for (int t = 0; t < 12; t++) {
                ulonglong2 vv = vr[t];
                fma2(o2[2*t],   p2, vv.x);
                fma2(o2[2*t+1], p2, vv.y);
            }
        }
    }

    // Write [b][c][n] layout: n = tid fast -> fully coalesced per c.
    const float inv = 1.0f / l;
    float* op = g_att + ((size_t)(b * CC + h * HD)) * NN + n;
#pragma unroll
    for (int t = 0; t < 24; t++) {
        float2 u = unpack2(o2[t]);
        op[(2*t)     * NN] = u.x * inv;
        op[(2*t + 1) * NN] = u.y * inv;
    }
}

// ---------------------------------------------------------------------------
// 4) Proj GEMM: out[b][c][n] = sum_k att[b][k][n] * proj_w[k][c] + pb[c]
//    M = c (384), N = n (8192), K = 384. Both A and B loads are k-major
//    coalesced; output stores are float4-coalesced along n.
// ---------------------------------------------------------------------------
__global__ __launch_bounds__(256) void proj_kernel(const float* __restrict__ w,
                                                   const float* __restrict__ pb,
                                                   float* __restrict__ out) {
    __shared__ __align__(16) float As[GBK][GBM];
    __shared__ __align__(16) float Bs[GBK][GBN];
    const int mBase = blockIdx.y * GBM;     // c
    const int nBase = blockIdx.x * GBN;     // global token index
    const int b  = nBase >> 10;
    const int n0 = nBase & 1023;
    const int tid = threadIdx.x;
    const int ty = tid >> 4, tx = tid & 15;
    u64 acc[8][4] = {};

    for (int k0 = 0; k0 < CC; k0 += GBK) {
#pragma unroll
        for (int i = tid; i < GBK * GBM; i += 256) {   // A[m=c][k] = w[k][c]
            int kk = i >> 7, mm = i & 127;
            As[kk][mm] = w[(k0 + kk) * CC + mBase + mm];
        }
#pragma unroll
        for (int i = tid; i < GBK * GBN; i += 256) {   // B[k][n] = att[b][k][n]
            int kk = i >> 7, nn = i & 127;
            Bs[kk][nn] = g_att[((size_t)(b * CC + k0 + kk)) * NN + n0 + nn];
        }
        __syncthreads();
#pragma unroll
        for (int kk = 0; kk < GBK; kk++) {
            float4 a0 = *(const float4*)&As[kk][ty * 8];
            float4 a1 = *(const float4*)&As[kk][ty * 8 + 4];
            ulonglong2 bq0 = *(const ulonglong2*)&Bs[kk][tx * 8];
            ulonglong2 bq1 = *(const ulonglong2*)&Bs[kk][tx * 8 + 4];
            u64 bp[4] = { bq0.x, bq0.y, bq1.x, bq1.y };
            u64 ad[8] = { pack2(a0.x,a0.x), pack2(a0.y,a0.y), pack2(a0.z,a0.z), pack2(a0.w,a0.w),
                          pack2(a1.x,a1.x), pack2(a1.y,a1.y), pack2(a1.z,a1.z), pack2(a1.w,a1.w) };
#pragma unroll
            for (int i = 0; i < 8; i++)
#pragma unroll
                for (int jp = 0; jp < 4; jp++) fma2(acc[i][jp], ad[i], bp[jp]);
        }
        __syncthreads();
    }

#pragma unroll
    for (int i = 0; i < 8; i++) {
        int c = mBase + ty * 8 + i;
        float pbv = pb[c];
        float vv[8];
#pragma unroll
        for (int jp = 0; jp < 4; jp++) {
            float2 u = unpack2(acc[i][jp]);
            vv[2*jp]   = u.x + pbv;
            vv[2*jp+1] = u.y + pbv;
        }
        float* p = out + ((size_t)(b * CC + c)) * NN + n0 + tx * 8;
        ((float4*)p)[0] = make_float4(vv[0], vv[1], vv[2], vv[3]);
        ((float4*)p)[1] = make_float4(vv[4], vv[5], vv[6], vv[7]);
    }
}

// ---------------------------------------------------------------------------
extern "C" void kernel_launch(void* const* d_in, const int* in_sizes, int n_in,
                              void* d_out, int out_size) {
    const float* x      = (const float*)d_in[0];
    const float* qkv_w  = (const float*)d_in[1];
    const float* qkv_b  = (const float*)d_in[2];
    const float* proj_w = (const float*)d_in[3];
    const float* proj_b = (const float*)d_in[4];
    const float* mlp_w1 = (const float*)d_in[5];
    const float* mlp_b1 = (const float*)d_in[6];
    const float* mlp_w2 = (const float*)d_in[7];
    const float* mlp_b2 = (const float*)d_in[8];
    float* out = (float*)d_out;

    bias_kernel<<<(NBIAS + 255) / 256, 256>>>(mlp_w1, mlp_b1, mlp_w2, mlp_b2);
    qkv_kernel<<<dim3(3 * CC / GBN, BB * NN / GBM), 256>>>(x, qkv_w, qkv_b);
    attn_kernel<<<dim3(NN / 128, NH, BB), 128>>>();
    proj_kernel<<<dim3(BB * NN / GBN, CC / GBM), 256>>>(proj_w, proj_b, out);
}

// round 8
// speedup vs baseline: 1.2753x; 1.1170x over previous
#include <cuda_runtime.h>
#include <cuda_bf16.h>
#include <math.h>
#include <stdint.h>

#define BB 8
#define CC 384
#define NN 1024
#define NH 8
#define HD 48
#define HID 192
#define NBIAS 3969
#define QK_SCALE 0.14433756729740643f  // 48^-0.5
#define NCHUNK 18          // K' = 1152 split dim / 64
#define MT_QKV 64          // 8192/128 token tiles
#define NT_QKV 9           // 1152/128
#define MT_PROJ 3          // 384/128
#define NT_PROJ 64

typedef unsigned long long u64;

// ---------------- packed f32x2 helpers (attention kernel) -------------------
__device__ __forceinline__ void fma2(u64 &d, u64 a, u64 b) {
    asm("fma.rn.f32x2 %0, %1, %2, %0;" : "+l"(d) : "l"(a), "l"(b));
}
__device__ __forceinline__ void mul2(u64 &d, u64 a, u64 b) {
    asm("mul.rn.f32x2 %0, %1, %2;" : "=l"(d) : "l"(a), "l"(b));
}
__device__ __forceinline__ void add2(u64 &d, u64 a, u64 b) {
    asm("add.rn.f32x2 %0, %1, %2;" : "=l"(d) : "l"(a), "l"(b));
}
__device__ __forceinline__ u64 pack2(float x, float y) {
    u64 r; asm("mov.b64 %0, {%1, %2};" : "=l"(r) : "f"(x), "f"(y)); return r;
}
__device__ __forceinline__ float2 unpack2(u64 v) {
    float2 r; asm("mov.b64 {%0, %1}, %2;" : "=f"(r.x), "=f"(r.y) : "l"(v)); return r;
}

// ---------------- mma.sync / ldmatrix helpers (arch-generic ISA) ------------
__device__ __forceinline__ uint32_t cvta_smem(const void* p) {
    uint32_t a;
    asm("{ .reg .u64 t; cvta.to.shared.u64 t, %1; cvt.u32.u64 %0, t; }" : "=r"(a) : "l"(p));
    return a;
}
__device__ __forceinline__ void ldsm4(uint32_t &r0, uint32_t &r1, uint32_t &r2,
                                      uint32_t &r3, uint32_t addr) {
    asm volatile("ldmatrix.sync.aligned.m8n8.x4.shared.b16 {%0,%1,%2,%3}, [%4];"
                 : "=r"(r0), "=r"(r1), "=r"(r2), "=r"(r3) : "r"(addr));
}
__device__ __forceinline__ void mma16816(float* c, uint32_t a0, uint32_t a1,
                                         uint32_t a2, uint32_t a3,
                                         uint32_t b0, uint32_t b1) {
    asm volatile(
        "mma.sync.aligned.m16n8k16.row.col.f32.bf16.bf16.f32 "
        "{%0,%1,%2,%3}, {%4,%5,%6,%7}, {%8,%9}, {%0,%1,%2,%3};"
        : "+f"(c[0]), "+f"(c[1]), "+f"(c[2]), "+f"(c[3])
        : "r"(a0), "r"(a1), "r"(a2), "r"(a3), "r"(b0), "r"(b1));
}

// ---------------- scratch globals (no runtime allocation allowed) -----------
__device__ float g_bias[NH * NBIAS];
__device__ float g_Q[BB*NH*NN*HD];             // [b][h][n][d], Q pre-scaled
__device__ float g_K[BB*NH*NN*HD];
__device__ float g_V[BB*NH*NN*HD];
__device__ float g_att[BB*NN*CC];              // [token][c] row-major
// pre-swizzled bf16 operand tiles: [tile][chunk][16KB smem-image]
// swizzle: byte = row*128 + ((g ^ (row&7))*16), row in [0,128), g in [0,8)
__device__ __nv_bfloat16 g_XA[(size_t)MT_QKV * NCHUNK * 8192];   // tokens (hi,hi,lo)
__device__ __nv_bfloat16 g_WQ[(size_t)NT_QKV * NCHUNK * 8192];   // qkv_w^T (hi,lo,hi)
__device__ __nv_bfloat16 g_AT[(size_t)NT_PROJ * NCHUNK * 8192];  // att (hi,hi,lo)
__device__ __nv_bfloat16 g_WP[(size_t)MT_PROJ * NCHUNK * 8192];  // proj_w^T (hi,lo,hi)

__device__ __forceinline__ unsigned sw128(unsigned off) {
    return off ^ ((off >> 3) & 0x70);
}
__device__ __forceinline__ uint4 pack8(const unsigned short* h) {
    uint4 u;
    u.x = h[0] | ((unsigned)h[1] << 16);
    u.y = h[2] | ((unsigned)h[3] << 16);
    u.z = h[4] | ((unsigned)h[5] << 16);
    u.w = h[6] | ((unsigned)h[7] << 16);
    return u;
}

// ---------------------------------------------------------------------------
// 1) Relative-bias MLP over the 63x63 unique relative offsets
// ---------------------------------------------------------------------------
__global__ void bias_kernel(const float* __restrict__ w1, const float* __restrict__ b1,
                            const float* __restrict__ w2, const float* __restrict__ b2) {
    int p = blockIdx.x * blockDim.x + threadIdx.x;
    if (p >= NBIAS) return;
    int dh = p / 63, dw = p % 63;
    float rh = (float)(dh - 31) * (1.0f / 31.0f);
    float rw = (float)(dw - 31) * (1.0f / 31.0f);
    float out[NH];
#pragma unroll
    for (int h = 0; h < NH; h++) out[h] = b2[h];
    for (int k = 0; k < HID; k++) {
        float pre = rh * w1[k] + rw * w1[HID + k] + b1[k];
        float g = 0.5f * pre * (1.0f + erff(pre * 0.70710678118654752f));
#pragma unroll
        for (int h = 0; h < NH; h++) out[h] += g * w2[k * NH + h];
    }
#pragma unroll
    for (int h = 0; h < NH; h++) g_bias[h * NBIAS + p] = out[h];
}

// ---------------------------------------------------------------------------
// 2a) x -> token operand tiles (A side of qkv GEMM): terms (hi,hi,lo)
// ---------------------------------------------------------------------------
__global__ __launch_bounds__(256) void conv_x(const float* __restrict__ x) {
    const int chunk = blockIdx.x, tile = blockIdx.y;
    const int term = chunk / 6;
    const int kbase = chunk * 64 - term * 384;
    const bool lo = (term == 2);
    __nv_bfloat16* dst = g_XA + ((size_t)(tile * NCHUNK + chunk)) * 8192;
    for (int idx = threadIdx.x; idx < 1024; idx += 256) {
        int r = idx & 127, g = idx >> 7;              // r fast -> coalesced along n
        int token = tile * 128 + r;
        int b = token >> 10, n = token & 1023;
        const float* s = x + ((size_t)(b * CC + kbase + g * 8)) * NN + n;
        unsigned short hh[8];
#pragma unroll
        for (int j = 0; j < 8; j++) {
            float v = s[(size_t)j * NN];
            __nv_bfloat16 h = __float2bfloat16(v);
            if (lo) h = __float2bfloat16(v - __bfloat162float(h));
            hh[j] = __bfloat16_as_ushort(h);
        }
        *(uint4*)((char*)dst + sw128((unsigned)(r * 128 + g * 16))) = pack8(hh);
    }
}

// 2b) weight^T -> B tiles: terms (hi,lo,hi). which: 0 -> g_WQ, 1 -> g_WP.
__global__ __launch_bounds__(256) void conv_w(const float* __restrict__ src, int ks, int which) {
    const int chunk = blockIdx.x, tile = blockIdx.y;
    const int term = chunk / 6;
    const int kbase = chunk * 64 - term * 384;
    const bool lo = (term == 1);
    __nv_bfloat16* dst = (which == 0 ? g_WQ : g_WP) + ((size_t)(tile * NCHUNK + chunk)) * 8192;
    for (int idx = threadIdx.x; idx < 1024; idx += 256) {
        int r = idx & 127, g = idx >> 7;              // r fast -> coalesced along row
        int row = tile * 128 + r;
        const float* s = src + row + (size_t)(kbase + g * 8) * ks;
        unsigned short hh[8];
#pragma unroll
        for (int j = 0; j < 8; j++) {
            float v = s[(size_t)j * ks];
            __nv_bfloat16 h = __float2bfloat16(v);
            if (lo) h = __float2bfloat16(v - __bfloat162float(h));
            hh[j] = __bfloat16_as_ushort(h);
        }
        *(uint4*)((char*)dst + sw128((unsigned)(r * 128 + g * 16))) = pack8(hh);
    }
}

// 2c) attention output [token][c] -> proj B tiles (hi,hi,lo)
__global__ __launch_bounds__(256) void conv_att() {
    const int chunk = blockIdx.x, tile = blockIdx.y;
    const int term = chunk / 6;
    const int kbase = chunk * 64 - term * 384;
    const bool lo = (term == 2);
    __nv_bfloat16* dst = g_AT + ((size_t)(tile * NCHUNK + chunk)) * 8192;
    for (int idx = threadIdx.x; idx < 1024; idx += 256) {
        int r = idx >> 3, g = idx & 7;                // k fast -> coalesced on row-major src
        const float* s = g_att + (size_t)(tile * 128 + r) * CC + kbase + g * 8;
        unsigned short hh[8];
#pragma unroll
        for (int j = 0; j < 8; j++) {
            float v = s[j];
            __nv_bfloat16 h = __float2bfloat16(v);
            if (lo) h = __float2bfloat16(v - __bfloat162float(h));
            hh[j] = __bfloat16_as_ushort(h);
        }
        *(uint4*)((char*)dst + sw128((unsigned)(r * 128 + g * 16))) = pack8(hh);
    }
}

// ---------------------------------------------------------------------------
// 3) mma.sync GEMM mainloop: C[128,128] = sum over 18 chunks of
//    A[128,64] @ B[128,64]^T, bf16 in / fp32 accum. 8 warps, warp tile 64x32.
// ---------------------------------------------------------------------------
__device__ __forceinline__ void mma_mainloop(const uint4* __restrict__ At,
                                             const uint4* __restrict__ Bt,
                                             uint4* sA4, uint4* sB4,
                                             uint32_t sA, uint32_t sB,
                                             int tid, int warp_m, int warp_n,
                                             float acc[4][4][4]) {
    const int lane = tid & 31;
    const int lrow = lane & 7;           // row within 8x8 matrix
    const int lmat = lane >> 3;          // which 8x8 matrix (0..3)
    const int rA0 = warp_m * 64 + ((lmat & 1) << 3) + lrow;   // + mt*16
    const int rB0 = warp_n * 32 + ((lmat & 1) << 3) + lrow;   // + np*16
    const int gHalf = lmat >> 1;                               // + ks*2

    for (int c = 0; c < NCHUNK; c++) {
        const uint4* Ac = At + c * 1024;
        const uint4* Bc = Bt + c * 1024;
#pragma unroll
        for (int i = tid; i < 1024; i += 256) { sA4[i] = Ac[i]; sB4[i] = Bc[i]; }
        __syncthreads();
#pragma unroll
        for (int ks = 0; ks < 4; ks++) {
            const int g = ks * 2 + gHalf;
            uint32_t a[4][4];
#pragma unroll
            for (int mt = 0; mt < 4; mt++) {
                int row = rA0 + mt * 16;
                uint32_t addr = sA + row * 128 + ((g ^ (row & 7)) << 4);
                ldsm4(a[mt][0], a[mt][1], a[mt][2], a[mt][3], addr);
            }
            uint32_t b[4][2];
#pragma unroll
            for (int np = 0; np < 2; np++) {
                int row = rB0 + np * 16;
                uint32_t addr = sB + row * 128 + ((g ^ (row & 7)) << 4);
                uint32_t r0, r1, r2, r3;
                ldsm4(r0, r1, r2, r3, addr);
                b[2*np][0] = r0; b[2*np][1] = r2;
                b[2*np+1][0] = r1; b[2*np+1][1] = r3;
            }
#pragma unroll
            for (int mt = 0; mt < 4; mt++)
#pragma unroll
                for (int nt = 0; nt < 4; nt++)
                    mma16816(acc[mt][nt], a[mt][0], a[mt][1], a[mt][2], a[mt][3],
                             b[nt][0], b[nt][1]);
        }
        __syncthreads();
    }
}

__global__ __launch_bounds__(256) void gemm_qkv_mma(const float* __restrict__ bias) {
    __shared__ __align__(16) uint4 sA4[1024];
    __shared__ __align__(16) uint4 sB4[1024];
    const int nTile = blockIdx.x, mTile = blockIdx.y;
    const int tid = threadIdx.x, lane = tid & 31, wid = tid >> 5;
    const int warp_m = wid & 1, warp_n = wid >> 1;

    float acc[4][4][4] = {};
    mma_mainloop(((const uint4*)g_XA) + (size_t)mTile * NCHUNK * 1024,
                 ((const uint4*)g_WQ) + (size_t)nTile * NCHUNK * 1024,
                 sA4, sB4, cvta_smem(sA4), cvta_smem(sB4),
                 tid, warp_m, warp_n, acc);

    // Epilogue: rows = tokens, cols = qkv output channels.
    const int which = (nTile * 128) / CC;            // tile never straddles Q/K/V
    float* dst = (which == 0) ? g_Q : (which == 1 ? g_K : g_V);
    const float scale = (which == 0) ? QK_SCALE : 1.0f;
    const int rbase = mTile * 128 + warp_m * 64 + (lane >> 2);
    const int cbase = nTile * 128 + warp_n * 32 + (lane & 3) * 2;
#pragma unroll
    for (int nt = 0; nt < 4; nt++) {
        int col = cbase + nt * 8;
        int c = col - which * CC;
        int head = c / HD, d = c - head * HD;        // col even -> pair stays in head
        float2 bb = *(const float2*)&bias[col];
#pragma unroll
        for (int mt = 0; mt < 4; mt++)
#pragma unroll
            for (int half = 0; half < 2; half++) {
                int token = rbase + mt * 16 + half * 8;
                int b = token >> 10, n = token & 1023;
                float2 v;
                v.x = (acc[mt][nt][half*2+0] + bb.x) * scale;
                v.y = (acc[mt][nt][half*2+1] + bb.y) * scale;
                *(float2*)(dst + ((size_t)((b * NH + head) * NN + n)) * HD + d) = v;
            }
    }
}

__global__ __launch_bounds__(256) void gemm_proj_mma(const float* __restrict__ pb,
                                                     float* __restrict__ out) {
    __shared__ __align__(16) uint4 sA4[1024];
    __shared__ __align__(16) uint4 sB4[1024];
    const int nTile = blockIdx.x, mTile = blockIdx.y;  // n: token tile, m: c tile
    const int tid = threadIdx.x, lane = tid & 31, wid = tid >> 5;
    const int warp_m = wid & 1, warp_n = wid >> 1;

    float acc[4][4][4] = {};
    mma_mainloop(((const uint4*)g_WP) + (size_t)mTile * NCHUNK * 1024,
                 ((const uint4*)g_AT) + (size_t)nTile * NCHUNK * 1024,
                 sA4, sB4, cvta_smem(sA4), cvta_smem(sB4),
                 tid, warp_m, warp_n, acc);

    // Epilogue: rows = c, cols = tokens -> out[b][c][n], float2 along n.
    const int b = (nTile * 128) >> 10;               // token tile within one batch
    const int crow0 = mTile * 128 + warp_m * 64 + (lane >> 2);
    const int tok0  = nTile * 128 + warp_n * 32 + (lane & 3) * 2;
#pragma unroll
    for (int mt = 0; mt < 4; mt++)
#pragma unroll
        for (int half = 0; half < 2; half++) {
            int crow = crow0 + mt * 16 + half * 8;
            float pbv = pb[crow];
            float* orow = out + ((size_t)(b * CC + crow)) * NN;
#pragma unroll
            for (int nt = 0; nt < 4; nt++) {
                int token = tok0 + nt * 8;
                float2 v;
                v.x = acc[mt][nt][half*2+0] + pbv;
                v.y = acc[mt][nt][half*2+1] + pbv;
                *(float2*)(orow + (token & 1023)) = v;
            }
        }
}

// ---------------------------------------------------------------------------
// 4) Attention: one thread per query, f32x2 packed dot/accumulate.
//    (proven R4 math; epilogue writes row-major [token][c] for conv_att)
// ---------------------------------------------------------------------------
#define TK 32

__global__ __launch_bounds__(128, 3) void attn_kernel() {
    __shared__ __align__(16) float Ks[TK * HD];
    __shared__ __align__(16) float Vs[TK * HD];
    __shared__ float sS[TK * 128];
    __shared__ float sBias[NBIAS];

    const int b = blockIdx.z, h = blockIdx.y, qb = blockIdx.x;
    const int tid = threadIdx.x;

    for (int i = tid; i < NBIAS; i += 128) sBias[i] = g_bias[h * NBIAS + i];

    const int n = qb * 128 + tid;
    const int ih = n >> 5, iw = n & 31;

    const float4* Qp = (const float4*)(g_Q + (((b * NH + h) * NN) + n) * HD);
    u64 q2[24];
#pragma unroll
    for (int t = 0; t < 12; t++) {
        float4 v = Qp[t];
        q2[2*t]   = pack2(v.x, v.y);
        q2[2*t+1] = pack2(v.z, v.w);
    }

    const float4* Kg = (const float4*)(g_K + ((b * NH + h) * NN) * HD);
    const float4* Vg = (const float4*)(g_V + ((b * NH + h) * NN) * HD);

    u64 o2[24] = {};
    float m = -1e30f, l = 0.0f;

    for (int kt = 0; kt < NN; kt += TK) {
        __syncthreads();
        const int base4 = kt * (HD / 4);
#pragma unroll
        for (int i = tid; i < TK * HD / 4; i += 128) {
            ((float4*)Ks)[i] = Kg[base4 + i];
            ((float4*)Vs)[i] = Vg[base4 + i];
        }
        __syncthreads();

        float mt = m;
#pragma unroll 4
        for (int j = 0; j < TK; j++) {
            const ulonglong2* kr = (const ulonglong2*)(Ks + j * HD);
            u64 sa = 0, sb = 0;
#pragma unroll
            for (int t = 0; t < 12; t++) {
                ulonglong2 kp = kr[t];
                fma2(sa, q2[2*t],   kp.x);
                fma2(sb, q2[2*t+1], kp.y);
            }
            add2(sa, sa, sb);
            float2 su = unpack2(sa);
            float s = su.x + su.y;
            int key = kt + j;
            int dhi = ih - (key >> 5) + 31;
            int dwi = iw - (key & 31) + 31;
            s += sBias[dhi * 63 + dwi];
            sS[j * 128 + tid] = s;
            mt = fmaxf(mt, s);
        }

        float alpha = __expf(m - mt);
        m = mt;
        l *= alpha;
        u64 a2 = pack2(alpha, alpha);
#pragma unroll
        for (int t = 0; t < 24; t++) mul2(o2[t], o2[t], a2);

#pragma unroll 2
        for (int j = 0; j < TK; j++) {
            float p = __expf(sS[j * 128 + tid] - m);
            l += p;
            u64 p2 = pack2(p, p);
            const ulonglong2* vr = (const ulonglong2*)(Vs + j * HD);
#pragma unroll
            for (int t = 0; t < 12; t++) {
                ulonglong2 vv = vr[t];
                fma2(o2[2*t],   p2, vv.x);
                fma2(o2[2*t+1], p2, vv.y);
            }
        }
    }

    const float inv = 1.0f / l;
    float* op = g_att + ((size_t)(b * NN + n)) * CC + h * HD;   // [token][c]
#pragma unroll
    for (int t = 0; t < 12; t++) {
        float2 u0 = unpack2(o2[2*t]);
        float2 u1 = unpack2(o2[2*t+1]);
        ((float4*)op)[t] = make_float4(u0.x * inv, u0.y * inv, u1.x * inv, u1.y * inv);
    }
}

// ---------------------------------------------------------------------------
extern "C" void kernel_launch(void* const* d_in, const int* in_sizes, int n_in,
                              void* d_out, int out_size) {
    const float* x      = (const float*)d_in[0];
    const float* qkv_w  = (const float*)d_in[1];
    const float* qkv_b  = (const float*)d_in[2];
    const float* proj_w = (const float*)d_in[3];
    const float* proj_b = (const float*)d_in[4];
    const float* mlp_w1 = (const float*)d_in[5];
    const float* mlp_b1 = (const float*)d_in[6];
    const float* mlp_w2 = (const float*)d_in[7];
    const float* mlp_b2 = (const float*)d_in[8];
    float* out = (float*)d_out;

    bias_kernel<<<(NBIAS + 255) / 256, 256>>>(mlp_w1, mlp_b1, mlp_w2, mlp_b2);
    conv_x<<<dim3(NCHUNK, MT_QKV), 256>>>(x);
    conv_w<<<dim3(NCHUNK, NT_QKV), 256>>>(qkv_w, 3 * CC, 0);
    conv_w<<<dim3(NCHUNK, MT_PROJ), 256>>>(proj_w, CC, 1);
    gemm_qkv_mma<<<dim3(NT_QKV, MT_QKV), 256>>>(qkv_b);
    attn_kernel<<<dim3(NN / 128, NH, BB), 128>>>();
    conv_att<<<dim3(NCHUNK, NT_PROJ), 256>>>();
    gemm_proj_mma<<<dim3(NT_PROJ, MT_PROJ), 256>>>(proj_b, out);
}

// round 9
// speedup vs baseline: 2.3474x; 1.8407x over previous
#include <cuda_runtime.h>
#include <cuda_bf16.h>
#include <math.h>
#include <stdint.h>

#define BB 8
#define CC 384
#define NN 1024
#define NH 8
#define HD 48
#define HID 192
#define NBIAS 3969
#define BIAS_STRIDE 4096
#define QK_SCALE 0.14433756729740643f  // 48^-0.5
#define NCHUNK 18          // K' = 1152 split dim / 64
#define MT_QKV 64
#define NT_QKV 9
#define MT_PROJ 3
#define NT_PROJ 64

// ---------------- PTX helpers ----------------------------------------------
__device__ __forceinline__ uint32_t cvta_smem(const void* p) {
    uint32_t a;
    asm("{ .reg .u64 t; cvta.to.shared.u64 t, %1; cvt.u32.u64 %0, t; }" : "=r"(a) : "l"(p));
    return a;
}
__device__ __forceinline__ void ldsm4(uint32_t &r0, uint32_t &r1, uint32_t &r2,
                                      uint32_t &r3, uint32_t addr) {
    asm volatile("ldmatrix.sync.aligned.m8n8.x4.shared.b16 {%0,%1,%2,%3}, [%4];"
                 : "=r"(r0), "=r"(r1), "=r"(r2), "=r"(r3) : "r"(addr));
}
__device__ __forceinline__ void ldsm4t(uint32_t &r0, uint32_t &r1, uint32_t &r2,
                                       uint32_t &r3, uint32_t addr) {
    asm volatile("ldmatrix.sync.aligned.m8n8.x4.trans.shared.b16 {%0,%1,%2,%3}, [%4];"
                 : "=r"(r0), "=r"(r1), "=r"(r2), "=r"(r3) : "r"(addr));
}
__device__ __forceinline__ void mma16816(float* c, uint32_t a0, uint32_t a1,
                                         uint32_t a2, uint32_t a3,
                                         uint32_t b0, uint32_t b1) {
    asm volatile(
        "mma.sync.aligned.m16n8k16.row.col.f32.bf16.bf16.f32 "
        "{%0,%1,%2,%3}, {%4,%5,%6,%7}, {%8,%9}, {%0,%1,%2,%3};"
        : "+f"(c[0]), "+f"(c[1]), "+f"(c[2]), "+f"(c[3])
        : "r"(a0), "r"(a1), "r"(a2), "r"(a3), "r"(b0), "r"(b1));
}
__device__ __forceinline__ void cp16(uint32_t dst, const void* src) {
    asm volatile("cp.async.cg.shared.global [%0], [%1], 16;" :: "r"(dst), "l"(src));
}
#define CP_COMMIT() asm volatile("cp.async.commit_group;")
#define CP_WAIT0()  asm volatile("cp.async.wait_group 0;")

// pack two f32 -> bf16x2 (lo in low half)
__device__ __forceinline__ uint32_t packbf2(float lo, float hi) {
    uint32_t r; asm("cvt.rn.bf16x2.f32 %0, %1, %2;" : "=r"(r) : "f"(hi), "f"(lo)); return r;
}
__device__ __forceinline__ float lo_as_f(uint32_t u) { return __uint_as_float(u << 16); }
__device__ __forceinline__ float hi_as_f(uint32_t u) { return __uint_as_float(u & 0xFFFF0000u); }

// ---------------- scratch globals (zero-init; no runtime alloc) -------------
__device__ float g_bias[NH * BIAS_STRIDE];
// split-bf16 swizzled tile images, [.. tile][split hi/lo][8192 bf16 = 16KB]
__device__ __nv_bfloat16 g_Qt[(size_t)BB*NH*8*2*8192];   // Q, pre-scaled
__device__ __nv_bfloat16 g_Kt[(size_t)BB*NH*8*2*8192];
__device__ __nv_bfloat16 g_Vt[(size_t)BB*NH*8*2*8192];
// GEMM operand images (chunk-major, terms as in R8)
__device__ __nv_bfloat16 g_XA[(size_t)MT_QKV * NCHUNK * 8192];   // tokens (hi,hi,lo)
__device__ __nv_bfloat16 g_WQ[(size_t)NT_QKV * NCHUNK * 8192];   // qkv_w^T (hi,lo,hi)
__device__ __nv_bfloat16 g_AT[(size_t)NT_PROJ * NCHUNK * 8192];  // attn out (hi,hi,lo)
__device__ __nv_bfloat16 g_WP[(size_t)MT_PROJ * NCHUNK * 8192];  // proj_w^T (hi,lo,hi)

__device__ __forceinline__ unsigned sw128(unsigned off) {
    return off ^ ((off >> 3) & 0x70);
}
__device__ __forceinline__ uint4 pack8(const unsigned short* h) {
    uint4 u;
    u.x = h[0] | ((unsigned)h[1] << 16);
    u.y = h[2] | ((unsigned)h[3] << 16);
    u.z = h[4] | ((unsigned)h[5] << 16);
    u.w = h[6] | ((unsigned)h[7] << 16);
    return u;
}

// ---------------------------------------------------------------------------
// 1) Relative-bias MLP over the 63x63 unique relative offsets
// ---------------------------------------------------------------------------
__global__ void bias_kernel(const float* __restrict__ w1, const float* __restrict__ b1,
                            const float* __restrict__ w2, const float* __restrict__ b2) {
    int p = blockIdx.x * blockDim.x + threadIdx.x;
    if (p >= NBIAS) return;
    int dh = p / 63, dw = p % 63;
    float rh = (float)(dh - 31) * (1.0f / 31.0f);
    float rw = (float)(dw - 31) * (1.0f / 31.0f);
    float out[NH];
#pragma unroll
    for (int h = 0; h < NH; h++) out[h] = b2[h];
    for (int k = 0; k < HID; k++) {
        float pre = rh * w1[k] + rw * w1[HID + k] + b1[k];
        float g = 0.5f * pre * (1.0f + erff(pre * 0.70710678118654752f));
#pragma unroll
        for (int h = 0; h < NH; h++) out[h] += g * w2[k * NH + h];
    }
#pragma unroll
    for (int h = 0; h < NH; h++) g_bias[h * BIAS_STRIDE + p] = out[h];
}

// ---------------------------------------------------------------------------
// 2a) x -> token operand tiles (A side of qkv GEMM): terms (hi,hi,lo)
// ---------------------------------------------------------------------------
__global__ __launch_bounds__(256) void conv_x(const float* __restrict__ x) {
    const int chunk = blockIdx.x, tile = blockIdx.y;
    const int term = chunk / 6;
    const int kbase = chunk * 64 - term * 384;
    const bool lo = (term == 2);
    __nv_bfloat16* dst = g_XA + ((size_t)(tile * NCHUNK + chunk)) * 8192;
    for (int idx = threadIdx.x; idx < 1024; idx += 256) {
        int r = idx & 127, g = idx >> 7;
        int token = tile * 128 + r;
        int b = token >> 10, n = token & 1023;
        const float* s = x + ((size_t)(b * CC + kbase + g * 8)) * NN + n;
        unsigned short hh[8];
#pragma unroll
        for (int j = 0; j < 8; j++) {
            float v = s[(size_t)j * NN];
            __nv_bfloat16 h = __float2bfloat16(v);
            if (lo) h = __float2bfloat16(v - __bfloat162float(h));
            hh[j] = __bfloat16_as_ushort(h);
        }
        *(uint4*)((char*)dst + sw128((unsigned)(r * 128 + g * 16))) = pack8(hh);
    }
}

// 2b) weight^T -> B tiles: terms (hi,lo,hi). which: 0 -> g_WQ, 1 -> g_WP.
__global__ __launch_bounds__(256) void conv_w(const float* __restrict__ src, int ks, int which) {
    const int chunk = blockIdx.x, tile = blockIdx.y;
    const int term = chunk / 6;
    const int kbase = chunk * 64 - term * 384;
    const bool lo = (term == 1);
    __nv_bfloat16* dst = (which == 0 ? g_WQ : g_WP) + ((size_t)(tile * NCHUNK + chunk)) * 8192;
    for (int idx = threadIdx.x; idx < 1024; idx += 256) {
        int r = idx & 127, g = idx >> 7;
        int row = tile * 128 + r;
        const float* s = src + row + (size_t)(kbase + g * 8) * ks;
        unsigned short hh[8];
#pragma unroll
        for (int j = 0; j < 8; j++) {
            float v = s[(size_t)j * ks];
            __nv_bfloat16 h = __float2bfloat16(v);
            if (lo) h = __float2bfloat16(v - __bfloat162float(h));
            hh[j] = __bfloat16_as_ushort(h);
        }
        *(uint4*)((char*)dst + sw128((unsigned)(r * 128 + g * 16))) = pack8(hh);
    }
}

// ---------------------------------------------------------------------------
// 3) mma.sync GEMM mainloop (as R8, proven)
// ---------------------------------------------------------------------------
__device__ __forceinline__ void mma_mainloop(const uint4* __restrict__ At,
                                             const uint4* __restrict__ Bt,
                                             uint4* sA4, uint4* sB4,
                                             uint32_t sA, uint32_t sB,
                                             int tid, int warp_m, int warp_n,
                                             float acc[4][4][4]) {
    const int lane = tid & 31;
    const int lrow = lane & 7;
    const int lmat = lane >> 3;
    const int rA0 = warp_m * 64 + ((lmat & 1) << 3) + lrow;
    const int rB0 = warp_n * 32 + ((lmat & 1) << 3) + lrow;
    const int gHalf = lmat >> 1;

    for (int c = 0; c < NCHUNK; c++) {
        const uint4* Ac = At + c * 1024;
        const uint4* Bc = Bt + c * 1024;
#pragma unroll
        for (int i = tid; i < 1024; i += 256) { sA4[i] = Ac[i]; sB4[i] = Bc[i]; }
        __syncthreads();
#pragma unroll
        for (int ks = 0; ks < 4; ks++) {
            const int g = ks * 2 + gHalf;
            uint32_t a[4][4];
#pragma unroll
            for (int mt = 0; mt < 4; mt++) {
                int row = rA0 + mt * 16;
                uint32_t addr = sA + row * 128 + ((g ^ (row & 7)) << 4);
                ldsm4(a[mt][0], a[mt][1], a[mt][2], a[mt][3], addr);
            }
            uint32_t b[4][2];
#pragma unroll
            for (int np = 0; np < 2; np++) {
                int row = rB0 + np * 16;
                uint32_t addr = sB + row * 128 + ((g ^ (row & 7)) << 4);
                uint32_t r0, r1, r2, r3;
                ldsm4(r0, r1, r2, r3, addr);
                b[2*np][0] = r0; b[2*np][1] = r2;
                b[2*np+1][0] = r1; b[2*np+1][1] = r3;
            }
#pragma unroll
            for (int mt = 0; mt < 4; mt++)
#pragma unroll
                for (int nt = 0; nt < 4; nt++)
                    mma16816(acc[mt][nt], a[mt][0], a[mt][1], a[mt][2], a[mt][3],
                             b[nt][0], b[nt][1]);
        }
        __syncthreads();
    }
}

// qkv GEMM: epilogue writes split-bf16 swizzled Q/K/V tile images.
__global__ __launch_bounds__(256) void gemm_qkv_mma(const float* __restrict__ bias) {
    __shared__ __align__(16) uint4 sA4[1024];
    __shared__ __align__(16) uint4 sB4[1024];
    const int nTile = blockIdx.x, mTile = blockIdx.y;
    const int tid = threadIdx.x, lane = tid & 31, wid = tid >> 5;
    const int warp_m = wid & 1, warp_n = wid >> 1;

    float acc[4][4][4] = {};
    mma_mainloop(((const uint4*)g_XA) + (size_t)mTile * NCHUNK * 1024,
                 ((const uint4*)g_WQ) + (size_t)nTile * NCHUNK * 1024,
                 sA4, sB4, cvta_smem(sA4), cvta_smem(sB4),
                 tid, warp_m, warp_n, acc);

    const int which = (nTile * 128) / CC;
    __nv_bfloat16* dst = (which == 0) ? g_Qt : (which == 1 ? g_Kt : g_Vt);
    const float scale = (which == 0) ? QK_SCALE : 1.0f;
    const int rbase = mTile * 128 + warp_m * 64 + (lane >> 2);
    const int cbase = nTile * 128 + warp_n * 32 + (lane & 3) * 2;
#pragma unroll
    for (int nt = 0; nt < 4; nt++) {
        int col = cbase + nt * 8;
        int c = col - which * CC;
        int head = c / HD, d = c - head * HD;        // c even -> pair stays in head
        float2 bb = *(const float2*)&bias[col];
#pragma unroll
        for (int mt = 0; mt < 4; mt++)
#pragma unroll
            for (int half = 0; half < 2; half++) {
                int token = rbase + mt * 16 + half * 8;
                int b = token >> 10, n = token & 1023;
                float vx = (acc[mt][nt][half*2+0] + bb.x) * scale;
                float vy = (acc[mt][nt][half*2+1] + bb.y) * scale;
                uint32_t hp = packbf2(vx, vy);
                uint32_t lp = packbf2(vx - lo_as_f(hp), vy - hi_as_f(hp));
                size_t img = ((size_t)((b * NH + head) * 8 + (n >> 7))) * 2;
                int row = n & 127;
                unsigned off = (unsigned)(row * 128) +
                               ((((unsigned)d >> 3) ^ (row & 7)) << 4) + (d & 7) * 2;
                *(uint32_t*)((char*)(dst + img * 8192) + off) = hp;
                *(uint32_t*)((char*)(dst + (img + 1) * 8192) + off) = lp;
            }
    }
}

// proj GEMM (unchanged from R8): out[b][c][n]
__global__ __launch_bounds__(256) void gemm_proj_mma(const float* __restrict__ pb,
                                                     float* __restrict__ out) {
    __shared__ __align__(16) uint4 sA4[1024];
    __shared__ __align__(16) uint4 sB4[1024];
    const int nTile = blockIdx.x, mTile = blockIdx.y;
    const int tid = threadIdx.x, lane = tid & 31, wid = tid >> 5;
    const int warp_m = wid & 1, warp_n = wid >> 1;

    float acc[4][4][4] = {};
    mma_mainloop(((const uint4*)g_WP) + (size_t)mTile * NCHUNK * 1024,
                 ((const uint4*)g_AT) + (size_t)nTile * NCHUNK * 1024,
                 sA4, sB4, cvta_smem(sA4), cvta_smem(sB4),
                 tid, warp_m, warp_n, acc);

    const int b = (nTile * 128) >> 10;
    const int crow0 = mTile * 128 + warp_m * 64 + (lane >> 2);
    const int tok0  = nTile * 128 + warp_n * 32 + (lane & 3) * 2;
#pragma unroll
    for (int mt = 0; mt < 4; mt++)
#pragma unroll
        for (int half = 0; half < 2; half++) {
            int crow = crow0 + mt * 16 + half * 8;
            float pbv = pb[crow];
            float* orow = out + ((size_t)(b * CC + crow)) * NN;
#pragma unroll
            for (int nt = 0; nt < 4; nt++) {
                int token = tok0 + nt * 8;
                float2 v;
                v.x = acc[mt][nt][half*2+0] + pbv;
                v.y = acc[mt][nt][half*2+1] + pbv;
                *(float2*)(orow + (token & 1023)) = v;
            }
        }
}

// ---------------------------------------------------------------------------
// 4) Tensor-core flash attention. CTA = 128 queries x (b,h). 8 warps.
//    smem: [0,16K) bias | [16K,48K) Q hi/lo | [48K..) 2 x {Kh,Kl,Vh,Vl} 64KB
// ---------------------------------------------------------------------------
#define ATTN_SMEM (16384 + 32768 + 2 * 65536)

__global__ __launch_bounds__(256) void attn_mma() {
    extern __shared__ char smem[];
    const int qt = blockIdx.x, h = blockIdx.y, b = blockIdx.z;
    const int tid = threadIdx.x, lane = tid & 31, warp = tid >> 5;
    const uint32_t sb = cvta_smem(smem);
    const uint32_t sQ = sb + 16384, sKV = sb + 49152;
    float* sBiasF = (float*)smem;

    const size_t bh = (size_t)(b * NH + h);

    // prologue: bias + Q tiles + K/V tile 0
    {
        const char* gB = (const char*)(g_bias + h * BIAS_STRIDE);
        for (int i = tid; i < 1024; i += 256) cp16(sb + i * 16, gB + i * 16);
        const char* gQ = (const char*)(g_Qt + (bh * 8 + qt) * 2 * 8192);
        for (int i = tid; i < 2048; i += 256) cp16(sQ + i * 16, gQ + i * 16);
        const char* gK = (const char*)(g_Kt + (bh * 8 + 0) * 2 * 8192);
        const char* gV = (const char*)(g_Vt + (bh * 8 + 0) * 2 * 8192);
        for (int i = tid; i < 2048; i += 256) cp16(sKV + i * 16, gK + i * 16);
        for (int i = tid; i < 2048; i += 256) cp16(sKV + 32768 + i * 16, gV + i * 16);
        CP_COMMIT();
        CP_WAIT0();
        __syncthreads();
    }

    // Q fragments (A, m16k16): warp owns 16 query rows.
    const int lrow = lane & 7, lmat = lane >> 3, gH = lmat >> 1;
    const int rowA = warp * 16 + ((lmat & 1) << 3) + lrow;
    uint32_t aQh[3][4], aQl[3][4];
#pragma unroll
    for (int ks = 0; ks < 3; ks++) {
        int g = 2 * ks + gH;
        uint32_t addr = sQ + rowA * 128 + ((g ^ (rowA & 7)) << 4);
        ldsm4(aQh[ks][0], aQh[ks][1], aQh[ks][2], aQh[ks][3], addr);
        ldsm4(aQl[ks][0], aQl[ks][1], aQl[ks][2], aQl[ks][3], addr + 16384);
    }

    const int q0 = qt * 128 + warp * 16 + (lane >> 2);
    const int q1 = q0 + 8;
    const int ih0 = q0 >> 5, iw0 = q0 & 31;
    const int ih1 = q1 >> 5, iw1 = q1 & 31;

    float Oacc[6][4] = {};
    float m0 = -1e30f, m1 = -1e30f, l0 = 0.0f, l1 = 0.0f;

    for (int kt = 0; kt < 8; kt++) {
        const uint32_t bufc = sKV + (kt & 1) * 65536;
        // prefetch next tile
        if (kt < 7) {
            const uint32_t bufn = sKV + ((kt + 1) & 1) * 65536;
            const char* gK = (const char*)(g_Kt + (bh * 8 + kt + 1) * 2 * 8192);
            const char* gV = (const char*)(g_Vt + (bh * 8 + kt + 1) * 2 * 8192);
            for (int i = tid; i < 2048; i += 256) cp16(bufn + i * 16, gK + i * 16);
            for (int i = tid; i < 2048; i += 256) cp16(bufn + 32768 + i * 16, gV + i * 16);
        }
        CP_COMMIT();

        // ---- S = Q K^T (3-term bf16 split), fp32 accum ----
        float S[16][4];
#pragma unroll
        for (int i = 0; i < 16; i++)
#pragma unroll
            for (int j = 0; j < 4; j++) S[i][j] = 0.0f;

#pragma unroll
        for (int kg = 0; kg < 8; kg++) {
            const int rowB = kg * 16 + ((lmat & 1) << 3) + lrow;
#pragma unroll
            for (int ks = 0; ks < 3; ks++) {
                int g = 2 * ks + gH;
                uint32_t addr = bufc + rowB * 128 + ((g ^ (rowB & 7)) << 4);
                uint32_t r0, r1, r2, r3;
                ldsm4(r0, r1, r2, r3, addr);                 // Kh
                mma16816(S[2*kg],   aQh[ks][0], aQh[ks][1], aQh[ks][2], aQh[ks][3], r0, r2);
                mma16816(S[2*kg+1], aQh[ks][0], aQh[ks][1], aQh[ks][2], aQh[ks][3], r1, r3);
                mma16816(S[2*kg],   aQl[ks][0], aQl[ks][1], aQl[ks][2], aQl[ks][3], r0, r2);
                mma16816(S[2*kg+1], aQl[ks][0], aQl[ks][1], aQl[ks][2], aQl[ks][3], r1, r3);
                uint32_t s0, s1, s2, s3;
                ldsm4(s0, s1, s2, s3, addr + 16384);         // Kl
                mma16816(S[2*kg],   aQh[ks][0], aQh[ks][1], aQh[ks][2], aQh[ks][3], s0, s2);
                mma16816(S[2*kg+1], aQh[ks][0], aQh[ks][1], aQh[ks][2], aQh[ks][3], s1, s3);
            }
        }

        // ---- bias + online softmax ----
        const int kb = kt * 128 + (lane & 3) * 2;
        float tm0 = -1e30f, tm1 = -1e30f;
#pragma unroll
        for (int nb = 0; nb < 16; nb++) {
            int k0 = kb + nb * 8, k1 = k0 + 1;
            int kh0 = k0 >> 5, kw0 = k0 & 31, kh1 = k1 >> 5, kw1 = k1 & 31;
            S[nb][0] += sBiasF[(ih0 - kh0 + 31) * 63 + (iw0 - kw0 + 31)];
            S[nb][1] += sBiasF[(ih0 - kh1 + 31) * 63 + (iw0 - kw1 + 31)];
            S[nb][2] += sBiasF[(ih1 - kh0 + 31) * 63 + (iw1 - kw0 + 31)];
            S[nb][3] += sBiasF[(ih1 - kh1 + 31) * 63 + (iw1 - kw1 + 31)];
            tm0 = fmaxf(tm0, fmaxf(S[nb][0], S[nb][1]));
            tm1 = fmaxf(tm1, fmaxf(S[nb][2], S[nb][3]));
        }
        tm0 = fmaxf(tm0, __shfl_xor_sync(0xFFFFFFFFu, tm0, 1));
        tm0 = fmaxf(tm0, __shfl_xor_sync(0xFFFFFFFFu, tm0, 2));
        tm1 = fmaxf(tm1, __shfl_xor_sync(0xFFFFFFFFu, tm1, 1));
        tm1 = fmaxf(tm1, __shfl_xor_sync(0xFFFFFFFFu, tm1, 2));
        float mn0 = fmaxf(m0, tm0), mn1 = fmaxf(m1, tm1);
        float al0 = __expf(m0 - mn0), al1 = __expf(m1 - mn1);
        m0 = mn0; m1 = mn1;
        l0 *= al0; l1 *= al1;
#pragma unroll
        for (int nb = 0; nb < 6; nb++) {
            Oacc[nb][0] *= al0; Oacc[nb][1] *= al0;
            Oacc[nb][2] *= al1; Oacc[nb][3] *= al1;
        }
        float ls0 = 0.0f, ls1 = 0.0f;
#pragma unroll
        for (int nb = 0; nb < 16; nb++) {
            S[nb][0] = __expf(S[nb][0] - m0); ls0 += S[nb][0];
            S[nb][1] = __expf(S[nb][1] - m0); ls0 += S[nb][1];
            S[nb][2] = __expf(S[nb][2] - m1); ls1 += S[nb][2];
            S[nb][3] = __expf(S[nb][3] - m1); ls1 += S[nb][3];
        }
        l0 += ls0; l1 += ls1;

        // ---- O += P V (3-term split); P frags built in-register ----
#pragma unroll
        for (int kg = 0; kg < 8; kg++) {
            uint32_t pa0 = packbf2(S[2*kg][0],   S[2*kg][1]);
            uint32_t pa1 = packbf2(S[2*kg][2],   S[2*kg][3]);
            uint32_t pa2 = packbf2(S[2*kg+1][0], S[2*kg+1][1]);
            uint32_t pa3 = packbf2(S[2*kg+1][2], S[2*kg+1][3]);
            uint32_t qa0 = packbf2(S[2*kg][0]   - lo_as_f(pa0), S[2*kg][1]   - hi_as_f(pa0));
            uint32_t qa1 = packbf2(S[2*kg][2]   - lo_as_f(pa1), S[2*kg][3]   - hi_as_f(pa1));
            uint32_t qa2 = packbf2(S[2*kg+1][0] - lo_as_f(pa2), S[2*kg+1][1] - hi_as_f(pa2));
            uint32_t qa3 = packbf2(S[2*kg+1][2] - lo_as_f(pa3), S[2*kg+1][3] - hi_as_f(pa3));
            const int rowV = kg * 16 + (lane & 15);
#pragma unroll
            for (int dp = 0; dp < 3; dp++) {
                int g = dp * 2 + (lane >> 4);
                uint32_t addr = bufc + 32768 + rowV * 128 + ((g ^ (rowV & 7)) << 4);
                uint32_t v0, v1, v2, v3;
                ldsm4t(v0, v1, v2, v3, addr);                // Vh (trans)
                mma16816(Oacc[2*dp],   pa0, pa1, pa2, pa3, v0, v1);
                mma16816(Oacc[2*dp+1], pa0, pa1, pa2, pa3, v2, v3);
                mma16816(Oacc[2*dp],   qa0, qa1, qa2, qa3, v0, v1);
                mma16816(Oacc[2*dp+1], qa0, qa1, qa2, qa3, v2, v3);
                uint32_t w0, w1, w2, w3;
                ldsm4t(w0, w1, w2, w3, addr + 16384);        // Vl (trans)
                mma16816(Oacc[2*dp],   pa0, pa1, pa2, pa3, w0, w1);
                mma16816(Oacc[2*dp+1], pa0, pa1, pa2, pa3, w2, w3);
            }
        }

        CP_WAIT0();
        __syncthreads();
    }

    // ---- finalize: l quad-reduction, write proj B-operand tiles (hi,hi,lo) ----
    l0 += __shfl_xor_sync(0xFFFFFFFFu, l0, 1);
    l0 += __shfl_xor_sync(0xFFFFFFFFu, l0, 2);
    l1 += __shfl_xor_sync(0xFFFFFFFFu, l1, 1);
    l1 += __shfl_xor_sync(0xFFFFFFFFu, l1, 2);
    const float inv0 = 1.0f / l0, inv1 = 1.0f / l1;

    const int token0 = b * NN + q0;
    const size_t tbase = (size_t)(token0 >> 7) * NCHUNK;
    const int row0 = token0 & 127;
#pragma unroll
    for (int nb = 0; nb < 6; nb++) {
        int d = nb * 8 + (lane & 3) * 2;
        int c = h * HD + d;
        int c6 = c >> 6;
        unsigned colc = (unsigned)(c & 63);
#pragma unroll
        for (int half = 0; half < 2; half++) {
            int row = row0 + half * 8;
            float vx = (half == 0 ? Oacc[nb][0] * inv0 : Oacc[nb][2] * inv1);
            float vy = (half == 0 ? Oacc[nb][1] * inv0 : Oacc[nb][3] * inv1);
            uint32_t hp = packbf2(vx, vy);
            uint32_t lp = packbf2(vx - lo_as_f(hp), vy - hi_as_f(hp));
            unsigned off = (unsigned)(row * 128) +
                           (((colc >> 3) ^ (row & 7)) << 4) + (colc & 7) * 2;
            *(uint32_t*)((char*)(g_AT + (tbase + c6) * 8192) + off) = hp;
            *(uint32_t*)((char*)(g_AT + (tbase + 6 + c6) * 8192) + off) = hp;
            *(uint32_t*)((char*)(g_AT + (tbase + 12 + c6) * 8192) + off) = lp;
        }
    }
}

// ---------------------------------------------------------------------------
extern "C" void kernel_launch(void* const* d_in, const int* in_sizes, int n_in,
                              void* d_out, int out_size) {
    const float* x      = (const float*)d_in[0];
    const float* qkv_w  = (const float*)d_in[1];
    const float* qkv_b  = (const float*)d_in[2];
    const float* proj_w = (const float*)d_in[3];
    const float* proj_b = (const float*)d_in[4];
    const float* mlp_w1 = (const float*)d_in[5];
    const float* mlp_b1 = (const float*)d_in[6];
    const float* mlp_w2 = (const float*)d_in[7];
    const float* mlp_b2 = (const float*)d_in[8];
    float* out = (float*)d_out;

    cudaFuncSetAttribute(attn_mma, cudaFuncAttributeMaxDynamicSharedMemorySize, ATTN_SMEM);

    bias_kernel<<<(NBIAS + 255) / 256, 256>>>(mlp_w1, mlp_b1, mlp_w2, mlp_b2);
    conv_x<<<dim3(NCHUNK, MT_QKV), 256>>>(x);
    conv_w<<<dim3(NCHUNK, NT_QKV), 256>>>(qkv_w, 3 * CC, 0);
    conv_w<<<dim3(NCHUNK, MT_PROJ), 256>>>(proj_w, CC, 1);
    gemm_qkv_mma<<<dim3(NT_QKV, MT_QKV), 256>>>(qkv_b);
    attn_mma<<<dim3(8, NH, BB), 256, ATTN_SMEM>>>();
    gemm_proj_mma<<<dim3(NT_PROJ, MT_PROJ), 256>>>(proj_b, out);
}

// round 10
// speedup vs baseline: 2.6532x; 1.1302x over previous
#include <cuda_runtime.h>
#include <cuda_bf16.h>
#include <math.h>
#include <stdint.h>

#define BB 8
#define CC 384
#define NN 1024
#define NH 8
#define HD 48
#define HID 192
#define NBIAS 3969
#define BIAS_STRIDE 4096
#define QK_SCALE 0.14433756729740643f  // 48^-0.5
#define NCHUNK 18          // K' = 1152 split dim / 64
#define MT_QKV 64
#define NT_QKV 9
#define MT_PROJ 3
#define NT_PROJ 64

// ---------------- PTX helpers ----------------------------------------------
__device__ __forceinline__ uint32_t cvta_smem(const void* p) {
    uint32_t a;
    asm("{ .reg .u64 t; cvta.to.shared.u64 t, %1; cvt.u32.u64 %0, t; }" : "=r"(a) : "l"(p));
    return a;
}
__device__ __forceinline__ void ldsm4(uint32_t &r0, uint32_t &r1, uint32_t &r2,
                                      uint32_t &r3, uint32_t addr) {
    asm volatile("ldmatrix.sync.aligned.m8n8.x4.shared.b16 {%0,%1,%2,%3}, [%4];"
                 : "=r"(r0), "=r"(r1), "=r"(r2), "=r"(r3) : "r"(addr));
}
__device__ __forceinline__ void ldsm4t(uint32_t &r0, uint32_t &r1, uint32_t &r2,
                                       uint32_t &r3, uint32_t addr) {
    asm volatile("ldmatrix.sync.aligned.m8n8.x4.trans.shared.b16 {%0,%1,%2,%3}, [%4];"
                 : "=r"(r0), "=r"(r1), "=r"(r2), "=r"(r3) : "r"(addr));
}
__device__ __forceinline__ void mma16816(float* c, uint32_t a0, uint32_t a1,
                                         uint32_t a2, uint32_t a3,
                                         uint32_t b0, uint32_t b1) {
    asm volatile(
        "mma.sync.aligned.m16n8k16.row.col.f32.bf16.bf16.f32 "
        "{%0,%1,%2,%3}, {%4,%5,%6,%7}, {%8,%9}, {%0,%1,%2,%3};"
        : "+f"(c[0]), "+f"(c[1]), "+f"(c[2]), "+f"(c[3])
        : "r"(a0), "r"(a1), "r"(a2), "r"(a3), "r"(b0), "r"(b1));
}
__device__ __forceinline__ void cp16(uint32_t dst, const void* src) {
    asm volatile("cp.async.cg.shared.global [%0], [%1], 16;" :: "r"(dst), "l"(src));
}
#define CP_COMMIT() asm volatile("cp.async.commit_group;")
#define CP_WAIT0()  asm volatile("cp.async.wait_group 0;")
#define CP_WAIT1()  asm volatile("cp.async.wait_group 1;")

// pack two f32 -> bf16x2 (lo in low half)
__device__ __forceinline__ uint32_t packbf2(float lo, float hi) {
    uint32_t r; asm("cvt.rn.bf16x2.f32 %0, %1, %2;" : "=r"(r) : "f"(hi), "f"(lo)); return r;
}
__device__ __forceinline__ float lo_as_f(uint32_t u) { return __uint_as_float(u << 16); }
__device__ __forceinline__ float hi_as_f(uint32_t u) { return __uint_as_float(u & 0xFFFF0000u); }

// ---------------- scratch globals (zero-init; no runtime alloc) -------------
__device__ float g_bias[NH * BIAS_STRIDE];
// split-bf16 swizzled tile images, [.. tile][split hi/lo][8192 bf16 = 16KB]
__device__ __nv_bfloat16 g_Qt[(size_t)BB*NH*8*2*8192];   // Q, pre-scaled
__device__ __nv_bfloat16 g_Kt[(size_t)BB*NH*8*2*8192];
__device__ __nv_bfloat16 g_Vt[(size_t)BB*NH*8*2*8192];
// GEMM operand images (chunk-major)
__device__ __nv_bfloat16 g_XA[(size_t)MT_QKV * NCHUNK * 8192];   // tokens (hi,hi,lo)
__device__ __nv_bfloat16 g_WQ[(size_t)NT_QKV * NCHUNK * 8192];   // qkv_w^T (hi,lo,hi)
__device__ __nv_bfloat16 g_AT[(size_t)NT_PROJ * NCHUNK * 8192];  // attn out (hi,hi,lo)
__device__ __nv_bfloat16 g_WP[(size_t)MT_PROJ * NCHUNK * 8192];  // proj_w^T (hi,lo,hi)

__device__ __forceinline__ unsigned sw128(unsigned off) {
    return off ^ ((off >> 3) & 0x70);
}
__device__ __forceinline__ uint4 pack8(const unsigned short* h) {
    uint4 u;
    u.x = h[0] | ((unsigned)h[1] << 16);
    u.y = h[2] | ((unsigned)h[3] << 16);
    u.z = h[4] | ((unsigned)h[5] << 16);
    u.w = h[6] | ((unsigned)h[7] << 16);
    return u;
}

// ---------------------------------------------------------------------------
// 1) Relative-bias MLP over the 63x63 unique relative offsets
// ---------------------------------------------------------------------------
__global__ void bias_kernel(const float* __restrict__ w1, const float* __restrict__ b1,
                            const float* __restrict__ w2, const float* __restrict__ b2) {
    int p = blockIdx.x * blockDim.x + threadIdx.x;
    if (p >= NBIAS) return;
    int dh = p / 63, dw = p % 63;
    float rh = (float)(dh - 31) * (1.0f / 31.0f);
    float rw = (float)(dw - 31) * (1.0f / 31.0f);
    float out[NH];
#pragma unroll
    for (int h = 0; h < NH; h++) out[h] = b2[h];
    for (int k = 0; k < HID; k++) {
        float pre = rh * w1[k] + rw * w1[HID + k] + b1[k];
        float g = 0.5f * pre * (1.0f + erff(pre * 0.70710678118654752f));
#pragma unroll
        for (int h = 0; h < NH; h++) out[h] += g * w2[k * NH + h];
    }
#pragma unroll
    for (int h = 0; h < NH; h++) g_bias[h * BIAS_STRIDE + p] = out[h];
}

// ---------------------------------------------------------------------------
// 2) Unified operand-conversion kernel (flattened grid: 18*(64+9+3) blocks)
//    role 0: x -> g_XA (hi,hi,lo)    role 1: qkv_w^T -> g_WQ (hi,lo,hi)
//    role 2: proj_w^T -> g_WP (hi,lo,hi)
// ---------------------------------------------------------------------------
__global__ __launch_bounds__(256) void conv_all(const float* __restrict__ x,
                                                const float* __restrict__ qkv_w,
                                                const float* __restrict__ proj_w) {
    int blk = blockIdx.x;
    int role, tile, chunk;
    if (blk < NCHUNK * MT_QKV)            { role = 0; tile = blk / NCHUNK; chunk = blk % NCHUNK; }
    else if (blk < NCHUNK * (MT_QKV + NT_QKV)) {
        int t = blk - NCHUNK * MT_QKV;      role = 1; tile = t / NCHUNK; chunk = t % NCHUNK;
    } else {
        int t = blk - NCHUNK * (MT_QKV + NT_QKV); role = 2; tile = t / NCHUNK; chunk = t % NCHUNK;
    }
    const int term = chunk / 6;
    const int kbase = chunk * 64 - term * 384;

    if (role == 0) {
        const bool lo = (term == 2);
        __nv_bfloat16* dst = g_XA + ((size_t)(tile * NCHUNK + chunk)) * 8192;
        for (int idx = threadIdx.x; idx < 1024; idx += 256) {
            int r = idx & 127, g = idx >> 7;
            int token = tile * 128 + r;
            int b = token >> 10, n = token & 1023;
            const float* s = x + ((size_t)(b * CC + kbase + g * 8)) * NN + n;
            unsigned short hh[8];
#pragma unroll
            for (int j = 0; j < 8; j++) {
                float v = s[(size_t)j * NN];
                __nv_bfloat16 h = __float2bfloat16(v);
                if (lo) h = __float2bfloat16(v - __bfloat162float(h));
                hh[j] = __bfloat16_as_ushort(h);
            }
            *(uint4*)((char*)dst + sw128((unsigned)(r * 128 + g * 16))) = pack8(hh);
        }
    } else {
        const bool lo = (term == 1);
        const float* src = (role == 1) ? qkv_w : proj_w;
        const int ks = (role == 1) ? 3 * CC : CC;
        __nv_bfloat16* dst = ((role == 1) ? g_WQ : g_WP) +
                             ((size_t)(tile * NCHUNK + chunk)) * 8192;
        for (int idx = threadIdx.x; idx < 1024; idx += 256) {
            int r = idx & 127, g = idx >> 7;
            int row = tile * 128 + r;
            const float* s = src + row + (size_t)(kbase + g * 8) * ks;
            unsigned short hh[8];
#pragma unroll
            for (int j = 0; j < 8; j++) {
                float v = s[(size_t)j * ks];
                __nv_bfloat16 h = __float2bfloat16(v);
                if (lo) h = __float2bfloat16(v - __bfloat162float(h));
                hh[j] = __bfloat16_as_ushort(h);
            }
            *(uint4*)((char*)dst + sw128((unsigned)(r * 128 + g * 16))) = pack8(hh);
        }
    }
}

// ---------------------------------------------------------------------------
// 3) cp.async double-buffered mma.sync GEMM mainloop.
//    smem: 2 x (A 16KB | B 16KB) ping-pong buffers.
// ---------------------------------------------------------------------------
__device__ __forceinline__ void mma_mainloop_pipe(const uint4* __restrict__ At,
                                                  const uint4* __restrict__ Bt,
                                                  uint32_t sBase,
                                                  int tid, int warp_m, int warp_n,
                                                  float acc[4][4][4]) {
    const int lane = tid & 31;
    const int lrow = lane & 7;
    const int lmat = lane >> 3;
    const int rA0 = warp_m * 64 + ((lmat & 1) << 3) + lrow;
    const int rB0 = warp_n * 32 + ((lmat & 1) << 3) + lrow;
    const int gHalf = lmat >> 1;

    // issue chunk c into buffer buf
    auto issue = [&](int c, int buf) {
        const uint4* Ac = At + c * 1024;
        const uint4* Bc = Bt + c * 1024;
        uint32_t base = sBase + buf * 32768;
#pragma unroll
        for (int i = tid; i < 1024; i += 256) cp16(base + i * 16, Ac + i);
#pragma unroll
        for (int i = tid; i < 1024; i += 256) cp16(base + 16384 + i * 16, Bc + i);
        CP_COMMIT();
    };

    issue(0, 0);
    for (int c = 0; c < NCHUNK; c++) {
        if (c + 1 < NCHUNK) { issue(c + 1, (c + 1) & 1); CP_WAIT1(); }
        else                { CP_WAIT0(); }
        __syncthreads();
        const uint32_t sA = sBase + (c & 1) * 32768;
        const uint32_t sB = sA + 16384;
#pragma unroll
        for (int ks = 0; ks < 4; ks++) {
            const int g = ks * 2 + gHalf;
            uint32_t a[4][4];
#pragma unroll
            for (int mt = 0; mt < 4; mt++) {
                int row = rA0 + mt * 16;
                uint32_t addr = sA + row * 128 + ((g ^ (row & 7)) << 4);
                ldsm4(a[mt][0], a[mt][1], a[mt][2], a[mt][3], addr);
            }
            uint32_t b[4][2];
#pragma unroll
            for (int np = 0; np < 2; np++) {
                int row = rB0 + np * 16;
                uint32_t addr = sB + row * 128 + ((g ^ (row & 7)) << 4);
                uint32_t r0, r1, r2, r3;
                ldsm4(r0, r1, r2, r3, addr);
                b[2*np][0] = r0; b[2*np][1] = r2;
                b[2*np+1][0] = r1; b[2*np+1][1] = r3;
            }
#pragma unroll
            for (int mt = 0; mt < 4; mt++)
#pragma unroll
                for (int nt = 0; nt < 4; nt++)
                    mma16816(acc[mt][nt], a[mt][0], a[mt][1], a[mt][2], a[mt][3],
                             b[nt][0], b[nt][1]);
        }
        __syncthreads();   // compute done before this buffer is refilled (c+2)
    }
}

// qkv GEMM: epilogue writes split-bf16 swizzled Q/K/V tile images.
__global__ __launch_bounds__(256) void gemm_qkv_mma(const float* __restrict__ bias) {
    __shared__ __align__(16) uint4 sbuf[4096];     // 64 KB ping-pong
    const int nTile = blockIdx.x, mTile = blockIdx.y;
    const int tid = threadIdx.x, lane = tid & 31, wid = tid >> 5;
    const int warp_m = wid & 1, warp_n = wid >> 1;

    float acc[4][4][4] = {};
    mma_mainloop_pipe(((const uint4*)g_XA) + (size_t)mTile * NCHUNK * 1024,
                      ((const uint4*)g_WQ) + (size_t)nTile * NCHUNK * 1024,
                      cvta_smem(sbuf), tid, warp_m, warp_n, acc);

    const int which = (nTile * 128) / CC;
    __nv_bfloat16* dst = (which == 0) ? g_Qt : (which == 1 ? g_Kt : g_Vt);
    const float scale = (which == 0) ? QK_SCALE : 1.0f;
    const int rbase = mTile * 128 + warp_m * 64 + (lane >> 2);
    const int cbase = nTile * 128 + warp_n * 32 + (lane & 3) * 2;
#pragma unroll
    for (int nt = 0; nt < 4; nt++) {
        int col = cbase + nt * 8;
        int c = col - which * CC;
        int head = c / HD, d = c - head * HD;        // c even -> pair stays in head
        float2 bb = *(const float2*)&bias[col];
#pragma unroll
        for (int mt = 0; mt < 4; mt++)
#pragma unroll
            for (int half = 0; half < 2; half++) {
                int token = rbase + mt * 16 + half * 8;
                int b = token >> 10, n = token & 1023;
                float vx = (acc[mt][nt][half*2+0] + bb.x) * scale;
                float vy = (acc[mt][nt][half*2+1] + bb.y) * scale;
                uint32_t hp = packbf2(vx, vy);
                uint32_t lp = packbf2(vx - lo_as_f(hp), vy - hi_as_f(hp));
                size_t img = ((size_t)((b * NH + head) * 8 + (n >> 7))) * 2;
                int row = n & 127;
                unsigned off = (unsigned)(row * 128) +
                               ((((unsigned)d >> 3) ^ (row & 7)) << 4) + (d & 7) * 2;
                *(uint32_t*)((char*)(dst + img * 8192) + off) = hp;
                *(uint32_t*)((char*)(dst + (img + 1) * 8192) + off) = lp;
            }
    }
}

// proj GEMM: out[b][c][n]
__global__ __launch_bounds__(256) void gemm_proj_mma(const float* __restrict__ pb,
                                                     float* __restrict__ out) {
    __shared__ __align__(16) uint4 sbuf[4096];
    const int nTile = blockIdx.x, mTile = blockIdx.y;
    const int tid = threadIdx.x, lane = tid & 31, wid = tid >> 5;
    const int warp_m = wid & 1, warp_n = wid >> 1;

    float acc[4][4][4] = {};
    mma_mainloop_pipe(((const uint4*)g_WP) + (size_t)mTile * NCHUNK * 1024,
                      ((const uint4*)g_AT) + (size_t)nTile * NCHUNK * 1024,
                      cvta_smem(sbuf), tid, warp_m, warp_n, acc);

    const int b = (nTile * 128) >> 10;
    const int crow0 = mTile * 128 + warp_m * 64 + (lane >> 2);
    const int tok0  = nTile * 128 + warp_n * 32 + (lane & 3) * 2;
#pragma unroll
    for (int mt = 0; mt < 4; mt++)
#pragma unroll
        for (int half = 0; half < 2; half++) {
            int crow = crow0 + mt * 16 + half * 8;
            float pbv = pb[crow];
            float* orow = out + ((size_t)(b * CC + crow)) * NN;
#pragma unroll
            for (int nt = 0; nt < 4; nt++) {
                int token = tok0 + nt * 8;
                float2 v;
                v.x = acc[mt][nt][half*2+0] + pbv;
                v.y = acc[mt][nt][half*2+1] + pbv;
                *(float2*)(orow + (token & 1023)) = v;
            }
        }
}

// ---------------------------------------------------------------------------
// 4) Tensor-core flash attention (proven R9). CTA = 128 queries x (b,h).
// ---------------------------------------------------------------------------
#define ATTN_SMEM (16384 + 32768 + 2 * 65536)

__global__ __launch_bounds__(256) void attn_mma() {
    extern __shared__ char smem[];
    const int qt = blockIdx.x, h = blockIdx.y, b = blockIdx.z;
    const int tid = threadIdx.x, lane = tid & 31, warp = tid >> 5;
    const uint32_t sb = cvta_smem(smem);
    const uint32_t sQ = sb + 16384, sKV = sb + 49152;
    float* sBiasF = (float*)smem;

    const size_t bh = (size_t)(b * NH + h);

    {
        const char* gB = (const char*)(g_bias + h * BIAS_STRIDE);
        for (int i = tid; i < 1024; i += 256) cp16(sb + i * 16, gB + i * 16);
        const char* gQ = (const char*)(g_Qt + (bh * 8 + qt) * 2 * 8192);
        for (int i = tid; i < 2048; i += 256) cp16(sQ + i * 16, gQ + i * 16);
        const char* gK = (const char*)(g_Kt + (bh * 8 + 0) * 2 * 8192);
        const char* gV = (const char*)(g_Vt + (bh * 8 + 0) * 2 * 8192);
        for (int i = tid; i < 2048; i += 256) cp16(sKV + i * 16, gK + i * 16);
        for (int i = tid; i < 2048; i += 256) cp16(sKV + 32768 + i * 16, gV + i * 16);
        CP_COMMIT();
        CP_WAIT0();
        __syncthreads();
    }

    const int lrow = lane & 7, lmat = lane >> 3, gH = lmat >> 1;
    const int rowA = warp * 16 + ((lmat & 1) << 3) + lrow;
    uint32_t aQh[3][4], aQl[3][4];
#pragma unroll
    for (int ks = 0; ks < 3; ks++) {
        int g = 2 * ks + gH;
        uint32_t addr = sQ + rowA * 128 + ((g ^ (rowA & 7)) << 4);
        ldsm4(aQh[ks][0], aQh[ks][1], aQh[ks][2], aQh[ks][3], addr);
        ldsm4(aQl[ks][0], aQl[ks][1], aQl[ks][2], aQl[ks][3], addr + 16384);
    }

    const int q0 = qt * 128 + warp * 16 + (lane >> 2);
    const int q1 = q0 + 8;
    const int ih0 = q0 >> 5, iw0 = q0 & 31;
    const int ih1 = q1 >> 5, iw1 = q1 & 31;

    float Oacc[6][4] = {};
    float m0 = -1e30f, m1 = -1e30f, l0 = 0.0f, l1 = 0.0f;

    for (int kt = 0; kt < 8; kt++) {
        const uint32_t bufc = sKV + (kt & 1) * 65536;
        if (kt < 7) {
            const uint32_t bufn = sKV + ((kt + 1) & 1) * 65536;
            const char* gK = (const char*)(g_Kt + (bh * 8 + kt + 1) * 2 * 8192);
            const char* gV = (const char*)(g_Vt + (bh * 8 + kt + 1) * 2 * 8192);
            for (int i = tid; i < 2048; i += 256) cp16(bufn + i * 16, gK + i * 16);
            for (int i = tid; i < 2048; i += 256) cp16(bufn + 32768 + i * 16, gV + i * 16);
        }
        CP_COMMIT();

        float S[16][4];
#pragma unroll
        for (int i = 0; i < 16; i++)
#pragma unroll
            for (int j = 0; j < 4; j++) S[i][j] = 0.0f;

#pragma unroll
        for (int kg = 0; kg < 8; kg++) {
            const int rowB = kg * 16 + ((lmat & 1) << 3) + lrow;
#pragma unroll
            for (int ks = 0; ks < 3; ks++) {
                int g = 2 * ks + gH;
                uint32_t addr = bufc + rowB * 128 + ((g ^ (rowB & 7)) << 4);
                uint32_t r0, r1, r2, r3;
                ldsm4(r0, r1, r2, r3, addr);                 // Kh
                mma16816(S[2*kg],   aQh[ks][0], aQh[ks][1], aQh[ks][2], aQh[ks][3], r0, r2);
                mma16816(S[2*kg+1], aQh[ks][0], aQh[ks][1], aQh[ks][2], aQh[ks][3], r1, r3);
                mma16816(S[2*kg],   aQl[ks][0], aQl[ks][1], aQl[ks][2], aQl[ks][3], r0, r2);
                mma16816(S[2*kg+1], aQl[ks][0], aQl[ks][1], aQl[ks][2], aQl[ks][3], r1, r3);
                uint32_t s0, s1, s2, s3;
                ldsm4(s0, s1, s2, s3, addr + 16384);         // Kl
                mma16816(S[2*kg],   aQh[ks][0], aQh[ks][1], aQh[ks][2], aQh[ks][3], s0, s2);
                mma16816(S[2*kg+1], aQh[ks][0], aQh[ks][1], aQh[ks][2], aQh[ks][3], s1, s3);
            }
        }

        const int kb = kt * 128 + (lane & 3) * 2;
        float tm0 = -1e30f, tm1 = -1e30f;
#pragma unroll
        for (int nb = 0; nb < 16; nb++) {
            int k0 = kb + nb * 8, k1 = k0 + 1;
            int kh0 = k0 >> 5, kw0 = k0 & 31, kh1 = k1 >> 5, kw1 = k1 & 31;
            S[nb][0] += sBiasF[(ih0 - kh0 + 31) * 63 + (iw0 - kw0 + 31)];
            S[nb][1] += sBiasF[(ih0 - kh1 + 31) * 63 + (iw0 - kw1 + 31)];
            S[nb][2] += sBiasF[(ih1 - kh0 + 31) * 63 + (iw1 - kw0 + 31)];
            S[nb][3] += sBiasF[(ih1 - kh1 + 31) * 63 + (iw1 - kw1 + 31)];
            tm0 = fmaxf(tm0, fmaxf(S[nb][0], S[nb][1]));
            tm1 = fmaxf(tm1, fmaxf(S[nb][2], S[nb][3]));
        }
        tm0 = fmaxf(tm0, __shfl_xor_sync(0xFFFFFFFFu, tm0, 1));
        tm0 = fmaxf(tm0, __shfl_xor_sync(0xFFFFFFFFu, tm0, 2));
        tm1 = fmaxf(tm1, __shfl_xor_sync(0xFFFFFFFFu, tm1, 1));
        tm1 = fmaxf(tm1, __shfl_xor_sync(0xFFFFFFFFu, tm1, 2));
        float mn0 = fmaxf(m0, tm0), mn1 = fmaxf(m1, tm1);
        float al0 = __expf(m0 - mn0), al1 = __expf(m1 - mn1);
        m0 = mn0; m1 = mn1;
        l0 *= al0; l1 *= al1;
#pragma unroll
        for (int nb = 0; nb < 6; nb++) {
            Oacc[nb][0] *= al0; Oacc[nb][1] *= al0;
            Oacc[nb][2] *= al1; Oacc[nb][3] *= al1;
        }
        float ls0 = 0.0f, ls1 = 0.0f;
#pragma unroll
        for (int nb = 0; nb < 16; nb++) {
            S[nb][0] = __expf(S[nb][0] - m0); ls0 += S[nb][0];
            S[nb][1] = __expf(S[nb][1] - m0); ls0 += S[nb][1];
            S[nb][2] = __expf(S[nb][2] - m1); ls1 += S[nb][2];
            S[nb][3] = __expf(S[nb][3] - m1); ls1 += S[nb][3];
        }
        l0 += ls0; l1 += ls1;

#pragma unroll
        for (int kg = 0; kg < 8; kg++) {
            uint32_t pa0 = packbf2(S[2*kg][0],   S[2*kg][1]);
            uint32_t pa1 = packbf2(S[2*kg][2],   S[2*kg][3]);
            uint32_t pa2 = packbf2(S[2*kg+1][0], S[2*kg+1][1]);
            uint32_t pa3 = packbf2(S[2*kg+1][2], S[2*kg+1][3]);
            uint32_t qa0 = packbf2(S[2*kg][0]   - lo_as_f(pa0), S[2*kg][1]   - hi_as_f(pa0));
            uint32_t qa1 = packbf2(S[2*kg][2]   - lo_as_f(pa1), S[2*kg][3]   - hi_as_f(pa1));
            uint32_t qa2 = packbf2(S[2*kg+1][0] - lo_as_f(pa2), S[2*kg+1][1] - hi_as_f(pa2));
            uint32_t qa3 = packbf2(S[2*kg+1][2] - lo_as_f(pa3), S[2*kg+1][3] - hi_as_f(pa3));
            const int rowV = kg * 16 + (lane & 15);
#pragma unroll
            for (int dp = 0; dp < 3; dp++) {
                int g = dp * 2 + (lane >> 4);
                uint32_t addr = bufc + 32768 + rowV * 128 + ((g ^ (rowV & 7)) << 4);
                uint32_t v0, v1, v2, v3;
                ldsm4t(v0, v1, v2, v3, addr);                // Vh (trans)
                mma16816(Oacc[2*dp],   pa0, pa1, pa2, pa3, v0, v1);
                mma16816(Oacc[2*dp+1], pa0, pa1, pa2, pa3, v2, v3);
                mma16816(Oacc[2*dp],   qa0, qa1, qa2, qa3, v0, v1);
                mma16816(Oacc[2*dp+1], qa0, qa1, qa2, qa3, v2, v3);
                uint32_t w0, w1, w2, w3;
                ldsm4t(w0, w1, w2, w3, addr + 16384);        // Vl (trans)
                mma16816(Oacc[2*dp],   pa0, pa1, pa2, pa3, w0, w1);
                mma16816(Oacc[2*dp+1], pa0, pa1, pa2, pa3, w2, w3);
            }
        }

        CP_WAIT0();
        __syncthreads();
    }

    l0 += __shfl_xor_sync(0xFFFFFFFFu, l0, 1);
    l0 += __shfl_xor_sync(0xFFFFFFFFu, l0, 2);
    l1 += __shfl_xor_sync(0xFFFFFFFFu, l1, 1);
    l1 += __shfl_xor_sync(0xFFFFFFFFu, l1, 2);
    const float inv0 = 1.0f / l0, inv1 = 1.0f / l1;

    const int token0 = b * NN + q0;
    const size_t tbase = (size_t)(token0 >> 7) * NCHUNK;
    const int row0 = token0 & 127;
#pragma unroll
    for (int nb = 0; nb < 6; nb++) {
        int d = nb * 8 + (lane & 3) * 2;
        int c = h * HD + d;
        int c6 = c >> 6;
        unsigned colc = (unsigned)(c & 63);
#pragma unroll
        for (int half = 0; half < 2; half++) {
            int row = row0 + half * 8;
            float vx = (half == 0 ? Oacc[nb][0] * inv0 : Oacc[nb][2] * inv1);
            float vy = (half == 0 ? Oacc[nb][1] * inv0 : Oacc[nb][3] * inv1);
            uint32_t hp = packbf2(vx, vy);
            uint32_t lp = packbf2(vx - lo_as_f(hp), vy - hi_as_f(hp));
            unsigned off = (unsigned)(row * 128) +
                           (((colc >> 3) ^ (row & 7)) << 4) + (colc & 7) * 2;
            *(uint32_t*)((char*)(g_AT + (tbase + c6) * 8192) + off) = hp;
            *(uint32_t*)((char*)(g_AT + (tbase + 6 + c6) * 8192) + off) = hp;
            *(uint32_t*)((char*)(g_AT + (tbase + 12 + c6) * 8192) + off) = lp;
        }
    }
}

// ---------------------------------------------------------------------------
extern "C" void kernel_launch(void* const* d_in, const int* in_sizes, int n_in,
                              void* d_out, int out_size) {
    const float* x      = (const float*)d_in[0];
    const float* qkv_w  = (const float*)d_in[1];
    const float* qkv_b  = (const float*)d_in[2];
    const float* proj_w = (const float*)d_in[3];
    const float* proj_b = (const float*)d_in[4];
    const float* mlp_w1 = (const float*)d_in[5];
    const float* mlp_b1 = (const float*)d_in[6];
    const float* mlp_w2 = (const float*)d_in[7];
    const float* mlp_b2 = (const float*)d_in[8];
    float* out = (float*)d_out;

    cudaFuncSetAttribute(attn_mma, cudaFuncAttributeMaxDynamicSharedMemorySize, ATTN_SMEM);

    bias_kernel<<<(NBIAS + 255) / 256, 256>>>(mlp_w1, mlp_b1, mlp_w2, mlp_b2);
    conv_all<<<NCHUNK * (MT_QKV + NT_QKV + MT_PROJ), 256>>>(x, qkv_w, proj_w);
    gemm_qkv_mma<<<dim3(NT_QKV, MT_QKV), 256>>>(qkv_b);
    attn_mma<<<dim3(8, NH, BB), 256, ATTN_SMEM>>>();
    gemm_proj_mma<<<dim3(NT_PROJ, MT_PROJ), 256>>>(proj_b, out);
}